// round 7
// baseline (speedup 1.0000x reference)
#include <cuda_runtime.h>
#include <cuda_bf16.h>
#include <cstdint>

#define BATCH 2
#define SEQ   2048
#define HID   1024
#define NHEAD 16
#define HDIM  64
#define SCALE 0.125f

// ---------------- device scratch (static allocations only) ----------------
__device__ __nv_bfloat16 g_xhi[BATCH * SEQ * HID];
__device__ __nv_bfloat16 g_xlo[BATCH * SEQ * HID];
__device__ __nv_bfloat16 g_whi[4 * HID * HID];   // transposed [N][K], mats q,k,v,o
__device__ __nv_bfloat16 g_wlo[4 * HID * HID];
__device__ __nv_bfloat16 g_chi[BATCH * SEQ * HID];
__device__ __nv_bfloat16 g_clo[BATCH * SEQ * HID];
__device__ __nv_bfloat16 g_qhi[BATCH * NHEAD * SEQ * HDIM];
__device__ __nv_bfloat16 g_qlo[BATCH * NHEAD * SEQ * HDIM];
__device__ __nv_bfloat16 g_khi[BATCH * NHEAD * SEQ * HDIM];
__device__ __nv_bfloat16 g_klo[BATCH * NHEAD * SEQ * HDIM];
__device__ __nv_bfloat16 g_vhi[BATCH * NHEAD * SEQ * HDIM];
__device__ __nv_bfloat16 g_vlo[BATCH * NHEAD * SEQ * HDIM];

// ---------------- helpers ----------------
__device__ __forceinline__ uint32_t smem_u32(const void* p) {
    uint32_t a;
    asm("{ .reg .u64 t; cvta.to.shared.u64 t, %1; cvt.u32.u64 %0, t; }" : "=r"(a) : "l"(p));
    return a;
}
__device__ __forceinline__ void ldsm_x4(uint32_t* r, uint32_t addr) {
    asm volatile("ldmatrix.sync.aligned.m8n8.x4.shared.b16 {%0,%1,%2,%3}, [%4];"
                 : "=r"(r[0]), "=r"(r[1]), "=r"(r[2]), "=r"(r[3]) : "r"(addr));
}
__device__ __forceinline__ void ldsm_x4_t(uint32_t* r, uint32_t addr) {
    asm volatile("ldmatrix.sync.aligned.m8n8.x4.trans.shared.b16 {%0,%1,%2,%3}, [%4];"
                 : "=r"(r[0]), "=r"(r[1]), "=r"(r[2]), "=r"(r[3]) : "r"(addr));
}
__device__ __forceinline__ void mma_bf16(float* c, const uint32_t* a, const uint32_t* b) {
    asm volatile(
        "mma.sync.aligned.m16n8k16.row.col.f32.bf16.bf16.f32 "
        "{%0,%1,%2,%3},{%4,%5,%6,%7},{%8,%9},{%0,%1,%2,%3};"
        : "+f"(c[0]), "+f"(c[1]), "+f"(c[2]), "+f"(c[3])
        : "r"(a[0]), "r"(a[1]), "r"(a[2]), "r"(a[3]), "r"(b[0]), "r"(b[1]));
}
__device__ __forceinline__ void split2(float a, float b, uint32_t& hi, uint32_t& lo) {
    __nv_bfloat162 h = __floats2bfloat162_rn(a, b);
    float2 hf = __bfloat1622float2(h);
    __nv_bfloat162 l = __floats2bfloat162_rn(a - hf.x, b - hf.y);
    hi = *(uint32_t*)&h;
    lo = *(uint32_t*)&l;
}
__device__ __forceinline__ void cp16(uint32_t dst, const void* src) {
    asm volatile("cp.async.cg.shared.global [%0], [%1], 16;" :: "r"(dst), "l"(src));
}
#define CP_COMMIT() asm volatile("cp.async.commit_group;" ::: "memory")
#define CP_WAIT0()  asm volatile("cp.async.wait_group 0;" ::: "memory")
#define CP_WAIT1()  asm volatile("cp.async.wait_group 1;" ::: "memory")

// ---------------- convert kernels ----------------
union BPack { __nv_bfloat16 b[8]; uint4 v; };

__global__ void split_rows_kernel(const float* __restrict__ in,
                                  __nv_bfloat16* __restrict__ hi,
                                  __nv_bfloat16* __restrict__ lo, int n8) {
    int i = blockIdx.x * blockDim.x + threadIdx.x;
    if (i >= n8) return;
    float f[8];
    *(float4*)(f)     = ((const float4*)in)[i * 2];
    *(float4*)(f + 4) = ((const float4*)in)[i * 2 + 1];
    BPack h, l;
#pragma unroll
    for (int j = 0; j < 8; ++j) {
        h.b[j] = __float2bfloat16(f[j]);
        l.b[j] = __float2bfloat16(f[j] - __bfloat162float(h.b[j]));
    }
    ((uint4*)hi)[i] = h.v;
    ((uint4*)lo)[i] = l.v;
}

__global__ void split_wT_kernel(const float* __restrict__ Wq, const float* __restrict__ Wk,
                                const float* __restrict__ Wv, const float* __restrict__ Wo) {
    __shared__ float t[32][33];
    const int mat = blockIdx.z;
    const float* W = (mat == 0) ? Wq : (mat == 1) ? Wk : (mat == 2) ? Wv : Wo;
    __nv_bfloat16* hi = g_whi + (size_t)mat * HID * HID;
    __nv_bfloat16* lo = g_wlo + (size_t)mat * HID * HID;
    const int n0 = blockIdx.x * 32, k0 = blockIdx.y * 32;
    const int tx = threadIdx.x, ty = threadIdx.y;
#pragma unroll
    for (int i = 0; i < 4; ++i)
        t[ty + 8 * i][tx] = W[(size_t)(k0 + ty + 8 * i) * HID + n0 + tx];
    __syncthreads();
#pragma unroll
    for (int i = 0; i < 4; ++i) {
        float v = t[tx][ty + 8 * i];
        __nv_bfloat16 h = __float2bfloat16(v);
        size_t idx = (size_t)(n0 + ty + 8 * i) * HID + k0 + tx;
        hi[idx] = h;
        lo[idx] = __float2bfloat16(v - __bfloat162float(h));
    }
}

// ---------------------------------------------------------------------------
// HMMA bf16 split GEMM, 2-stage cp.async pipeline, product-major MMA order.
// ---------------------------------------------------------------------------
#define TILEB 10240   // 128 rows * 80 bytes

__global__ __launch_bounds__(256, 2) void hgemm_kernel(
    const __nv_bfloat16* __restrict__ Ahi, const __nv_bfloat16* __restrict__ Alo,
    int mode, const int* __restrict__ pos_ids,
    const float* __restrict__ cosb, const float* __restrict__ sinb,
    float* __restrict__ outp)
{
    extern __shared__ char dsm[];
    const uint32_t S0 = smem_u32(dsm);

    const int tid = threadIdx.x;
    const int lane = tid & 31, wid = tid >> 5;
    const int wm = wid & 3, wn = wid >> 2;
    const int z = blockIdx.z;
    const int row0 = blockIdx.y << 7, col0 = blockIdx.x << 7;
    const int wsel = (mode == 0) ? z : 3;
    const __nv_bfloat16* Bhi = g_whi + (size_t)wsel * HID * HID;
    const __nv_bfloat16* Blo = g_wlo + (size_t)wsel * HID * HID;

    float acc[2][8][4];
#pragma unroll
    for (int t = 0; t < 2; ++t)
#pragma unroll
        for (int j = 0; j < 8; ++j)
#pragma unroll
            for (int e = 0; e < 4; ++e) acc[t][j][e] = 0.f;

    const int lrow = tid >> 1;
    const int lch  = (tid & 1) * 2;
    const uint32_t s_off = lrow * 80 + lch * 16;

    const int a_row = wm * 32 + (lane & 15);
    const int a_ch  = lane >> 4;
    const int b_row = wn * 64 + (lane & 7) + ((lane & 16) >> 1);
    const int b_ch  = (lane >> 3) & 1;

    auto stage_load = [&](int it, int s) {
        const int k0 = it * 32;
        const size_t ga = (size_t)(row0 + lrow) * HID + k0 + lch * 8;
        const size_t gb = (size_t)(col0 + lrow) * HID + k0 + lch * 8;
        const uint32_t d = S0 + s * (4 * TILEB) + s_off;
        cp16(d,                 Ahi + ga); cp16(d + 16,             Ahi + ga + 8);
        cp16(d + TILEB,         Alo + ga); cp16(d + TILEB + 16,     Alo + ga + 8);
        cp16(d + 2 * TILEB,     Bhi + gb); cp16(d + 2 * TILEB + 16, Bhi + gb + 8);
        cp16(d + 3 * TILEB,     Blo + gb); cp16(d + 3 * TILEB + 16, Blo + gb + 8);
    };

    stage_load(0, 0);
    CP_COMMIT();

    for (int it = 0; it < HID / 32; ++it) {
        const int s = it & 1;
        if (it + 1 < HID / 32) {
            stage_load(it + 1, s ^ 1);
            CP_COMMIT();
            CP_WAIT1();
        } else {
            CP_WAIT0();
        }
        __syncthreads();

        const uint32_t uAh = S0 + s * (4 * TILEB);
        const uint32_t uAl = uAh + TILEB;
        const uint32_t uBh = uAh + 2 * TILEB;
        const uint32_t uBl = uAh + 3 * TILEB;
#pragma unroll
        for (int kh = 0; kh < 2; ++kh) {
            uint32_t aH[2][4], aL[2][4], bH[4][4], bL[4][4];
            const uint32_t a_off = a_row * 80 + (kh * 2 + a_ch) * 16;
            const uint32_t b_off = b_row * 80 + (kh * 2 + b_ch) * 16;
            ldsm_x4(aH[0], uAh + a_off);
            ldsm_x4(aH[1], uAh + a_off + 16 * 80);
            ldsm_x4(aL[0], uAl + a_off);
            ldsm_x4(aL[1], uAl + a_off + 16 * 80);
#pragma unroll
            for (int g = 0; g < 4; ++g) {
                ldsm_x4(bH[g], uBh + b_off + g * (16 * 80));
                ldsm_x4(bL[g], uBl + b_off + g * (16 * 80));
            }
#pragma unroll
            for (int t = 0; t < 2; ++t)
#pragma unroll
                for (int g = 0; g < 4; ++g) {
                    mma_bf16(acc[t][2 * g],     aH[t], &bH[g][0]);
                    mma_bf16(acc[t][2 * g + 1], aH[t], &bH[g][2]);
                }
#pragma unroll
            for (int t = 0; t < 2; ++t)
#pragma unroll
                for (int g = 0; g < 4; ++g) {
                    mma_bf16(acc[t][2 * g],     aH[t], &bL[g][0]);
                    mma_bf16(acc[t][2 * g + 1], aH[t], &bL[g][2]);
                }
#pragma unroll
            for (int t = 0; t < 2; ++t)
#pragma unroll
                for (int g = 0; g < 4; ++g) {
                    mma_bf16(acc[t][2 * g],     aL[t], &bH[g][0]);
                    mma_bf16(acc[t][2 * g + 1], aL[t], &bH[g][2]);
                }
        }
        __syncthreads();
    }

    // ---------------- epilogue ----------------
    const int q2 = (lane & 3) * 2;
#pragma unroll
    for (int t = 0; t < 2; ++t) {
#pragma unroll
        for (int h2 = 0; h2 < 2; ++h2) {
            const int row = row0 + wm * 32 + t * 16 + (lane >> 2) + h2 * 8;
            if (mode == 1) {
                float* dst = outp + (size_t)row * HID + col0 + wn * 64 + q2;
#pragma unroll
                for (int j = 0; j < 8; ++j)
                    *(float2*)(dst + j * 8) =
                        make_float2(acc[t][j][h2 * 2], acc[t][j][h2 * 2 + 1]);
            } else {
                const int b_ = row >> 11, s_ = row & (SEQ - 1);
                const int h = (col0 >> 6) + wn;
                const size_t base = ((size_t)(b_ * NHEAD + h) * SEQ + s_) * HDIM;
                if (z == 2) {
#pragma unroll
                    for (int j = 0; j < 8; ++j) {
                        uint32_t hi, lo;
                        split2(acc[t][j][h2 * 2], acc[t][j][h2 * 2 + 1], hi, lo);
                        *(uint32_t*)(g_vhi + base + j * 8 + q2) = hi;
                        *(uint32_t*)(g_vlo + base + j * 8 + q2) = lo;
                    }
                } else {
                    const int pos = pos_ids[b_ * SEQ + s_];
                    const float* cr = cosb + pos * HDIM;
                    const float* sr = sinb + pos * HDIM;
                    __nv_bfloat16* dhi = (z == 0) ? g_qhi : g_khi;
                    __nv_bfloat16* dlo = (z == 0) ? g_qlo : g_klo;
                    const float sc_ = (z == 0) ? SCALE : 1.0f;
#pragma unroll
                    for (int j = 0; j < 4; ++j) {
                        float o1[2], o2[2];
#pragma unroll
                        for (int e = 0; e < 2; ++e) {
                            const int d = j * 8 + q2 + e;
                            const float x = acc[t][j][h2 * 2 + e];
                            const float y = acc[t][j + 4][h2 * 2 + e];
                            o1[e] = (x * cr[d] - y * sr[d]) * sc_;
                            o2[e] = (y * cr[d + 32] + x * sr[d + 32]) * sc_;
                        }
                        uint32_t hi, lo;
                        split2(o1[0], o1[1], hi, lo);
                        *(uint32_t*)(dhi + base + j * 8 + q2) = hi;
                        *(uint32_t*)(dlo + base + j * 8 + q2) = lo;
                        split2(o2[0], o2[1], hi, lo);
                        *(uint32_t*)(dhi + base + j * 8 + q2 + 32) = hi;
                        *(uint32_t*)(dlo + base + j * 8 + q2 + 32) = lo;
                    }
                }
            }
        }
    }
}

// ---------------------------------------------------------------------------
// HMMA flash attention, 2-stage cp.async pipeline, 2 CTAs/SM target.
// ---------------------------------------------------------------------------
#define AP  144    // bytes per smem row (64 bf16 + pad)
#define KT_ 9216   // 64 rows * AP

__global__ __launch_bounds__(256, 2) void attn_kernel()
{
    extern __shared__ char dsm[];
    const uint32_t S0 = smem_u32(dsm);

    const int tid = threadIdx.x, lane = tid & 31, wid = tid >> 5;
    const int qi = gridDim.x - 1 - blockIdx.x;
    const int h = blockIdx.y, b_ = blockIdx.z;
    const int q0 = qi << 7;
    const size_t hb = (size_t)(b_ * NHEAD + h) * SEQ * HDIM;
    const __nv_bfloat16 *qhi = g_qhi + hb, *qlo = g_qlo + hb;
    const __nv_bfloat16 *khi = g_khi + hb, *klo = g_klo + hb;
    const __nv_bfloat16 *vhi = g_vhi + hb, *vlo = g_vlo + hb;

    // ---- stage Q into stage-0 buffers via cp.async ----
    {
        const int r = tid >> 1, half = tid & 1;
        const __nv_bfloat16* sh = qhi + (size_t)(q0 + r) * HDIM + half * 32;
        const __nv_bfloat16* sl = qlo + (size_t)(q0 + r) * HDIM + half * 32;
        const uint32_t dh = S0 + ((r < 64) ? 0 : 2 * KT_) + (r & 63) * AP + half * 64;
        const uint32_t dl = dh + KT_;
#pragma unroll
        for (int c = 0; c < 4; ++c) {
            cp16(dh + c * 16, sh + c * 8);
            cp16(dl + c * 16, sl + c * 8);
        }
    }
    CP_COMMIT();
    CP_WAIT0();
    __syncthreads();

    // ---- Q fragments ----
    uint32_t qfh[4][4], qfl[4][4];
    {
        const uint32_t bh = S0 + ((wid < 4) ? 0 : 2 * KT_);
        const uint32_t bl = bh + KT_;
        const int arow = (wid & 3) * 16 + (lane & 15);
        const int ach = lane >> 4;
#pragma unroll
        for (int kc = 0; kc < 4; ++kc) {
            const uint32_t off = arow * AP + (kc * 2 + ach) * 16;
            ldsm_x4(qfh[kc], bh + off);
            ldsm_x4(qfl[kc], bl + off);
        }
    }
    __syncthreads();

    float oacc[8][4];
#pragma unroll
    for (int g = 0; g < 8; ++g)
#pragma unroll
        for (int e = 0; e < 4; ++e) oacc[g][e] = 0.f;
    float m0 = -1e30f, m1 = -1e30f, l0 = 0.f, l1 = 0.f;

    const int wbase = q0 + wid * 16;
    const int nt = (q0 >> 6) + 2;
    const int lrow = tid >> 2, lq = tid & 3;
    const int brow_ = (lane & 7) + ((lane & 16) >> 1);
    const int bch_ = (lane >> 3) & 1;
    const int vrow_ = lane & 15;
    const int vcol_ = (lane & 16) ? 8 : 0;

    auto kv_load = [&](int kt, int s) {
        const int k0 = kt << 6;
        const size_t src = (size_t)(k0 + lrow) * HDIM + lq * 16;
        const uint32_t d = S0 + s * (4 * KT_) + lrow * AP + lq * 32;
        cp16(d,                khi + src); cp16(d + 16,            khi + src + 8);
        cp16(d + KT_,          klo + src); cp16(d + KT_ + 16,      klo + src + 8);
        cp16(d + 2 * KT_,      vhi + src); cp16(d + 2 * KT_ + 16,  vhi + src + 8);
        cp16(d + 3 * KT_,      vlo + src); cp16(d + 3 * KT_ + 16,  vlo + src + 8);
    };

    kv_load(0, 0);
    CP_COMMIT();

    for (int kt = 0; kt < nt; ++kt) {
        const int k0 = kt << 6;
        const int s = kt & 1;
        if (kt + 1 < nt) {
            kv_load(kt + 1, s ^ 1);
            CP_COMMIT();
            CP_WAIT1();
        } else {
            CP_WAIT0();
        }
        __syncthreads();

        if (k0 <= wbase + 15) {
            const uint32_t uKh = S0 + s * (4 * KT_);
            const uint32_t uKl = uKh + KT_;
            const uint32_t uVh = uKh + 2 * KT_;
            const uint32_t uVl = uKh + 3 * KT_;

            // ---- S = Q K^T ----
            float sc[8][4];
#pragma unroll
            for (int g = 0; g < 8; ++g)
#pragma unroll
                for (int e = 0; e < 4; ++e) sc[g][e] = 0.f;
#pragma unroll
            for (int kc = 0; kc < 4; ++kc) {
#pragma unroll
                for (int g = 0; g < 4; ++g) {
                    uint32_t bH[4], bL[4];
                    const uint32_t boff = (g * 16 + brow_) * AP + (kc * 2 + bch_) * 16;
                    ldsm_x4(bH, uKh + boff);
                    ldsm_x4(bL, uKl + boff);
                    mma_bf16(sc[2 * g],     qfh[kc], &bH[0]);
                    mma_bf16(sc[2 * g + 1], qfh[kc], &bH[2]);
                    mma_bf16(sc[2 * g],     qfh[kc], &bL[0]);
                    mma_bf16(sc[2 * g + 1], qfh[kc], &bL[2]);
                    mma_bf16(sc[2 * g],     qfl[kc], &bH[0]);
                    mma_bf16(sc[2 * g + 1], qfl[kc], &bH[2]);
                }
            }

            // ---- causal mask ----
            const int r0 = wbase + (lane >> 2), r1 = r0 + 8;
            if (k0 + 63 > wbase) {
#pragma unroll
                for (int g = 0; g < 8; ++g) {
#pragma unroll
                    for (int e = 0; e < 2; ++e) {
                        const int col = k0 + 8 * g + 2 * (lane & 3) + e;
                        if (col > r0) sc[g][e] = -1e9f;
                        if (col > r1) sc[g][2 + e] = -1e9f;
                    }
                }
            }

            // ---- online softmax ----
            float mx0 = sc[0][0], mx1 = sc[0][2];
#pragma unroll
            for (int g = 0; g < 8; ++g) {
                mx0 = fmaxf(mx0, fmaxf(sc[g][0], sc[g][1]));
                mx1 = fmaxf(mx1, fmaxf(sc[g][2], sc[g][3]));
            }
            mx0 = fmaxf(mx0, __shfl_xor_sync(0xffffffffu, mx0, 1));
            mx0 = fmaxf(mx0, __shfl_xor_sync(0xffffffffu, mx0, 2));
            mx1 = fmaxf(mx1, __shfl_xor_sync(0xffffffffu, mx1, 1));
            mx1 = fmaxf(mx1, __shfl_xor_sync(0xffffffffu, mx1, 2));
            const float nm0 = fmaxf(m0, mx0), nm1 = fmaxf(m1, mx1);
            const float cr0 = __expf(m0 - nm0), cr1 = __expf(m1 - nm1);
            m0 = nm0; m1 = nm1;
            float rs0 = 0.f, rs1 = 0.f;
#pragma unroll
            for (int g = 0; g < 8; ++g) {
                sc[g][0] = __expf(sc[g][0] - nm0);
                sc[g][1] = __expf(sc[g][1] - nm0);
                sc[g][2] = __expf(sc[g][2] - nm1);
                sc[g][3] = __expf(sc[g][3] - nm1);
                rs0 += sc[g][0] + sc[g][1];
                rs1 += sc[g][2] + sc[g][3];
            }
            rs0 += __shfl_xor_sync(0xffffffffu, rs0, 1);
            rs0 += __shfl_xor_sync(0xffffffffu, rs0, 2);
            rs1 += __shfl_xor_sync(0xffffffffu, rs1, 1);
            rs1 += __shfl_xor_sync(0xffffffffu, rs1, 2);
            l0 = l0 * cr0 + rs0;
            l1 = l1 * cr1 + rs1;
#pragma unroll
            for (int g = 0; g < 8; ++g) {
                oacc[g][0] *= cr0; oacc[g][1] *= cr0;
                oacc[g][2] *= cr1; oacc[g][3] *= cr1;
            }

            // ---- P fragments (hi/lo) ----
            uint32_t pah[4][4], pal[4][4];
#pragma unroll
            for (int kc = 0; kc < 4; ++kc) {
                split2(sc[2 * kc][0],     sc[2 * kc][1],     pah[kc][0], pal[kc][0]);
                split2(sc[2 * kc][2],     sc[2 * kc][3],     pah[kc][1], pal[kc][1]);
                split2(sc[2 * kc + 1][0], sc[2 * kc + 1][1], pah[kc][2], pal[kc][2]);
                split2(sc[2 * kc + 1][2], sc[2 * kc + 1][3], pah[kc][3], pal[kc][3]);
            }

            // ---- O += P V ----
#pragma unroll
            for (int kc = 0; kc < 4; ++kc) {
#pragma unroll
                for (int dg = 0; dg < 4; ++dg) {
                    uint32_t vH[4], vL[4];
                    const uint32_t voff = (kc * 16 + vrow_) * AP + (dg * 16 + vcol_) * 2;
                    ldsm_x4_t(vH, uVh + voff);
                    ldsm_x4_t(vL, uVl + voff);
                    mma_bf16(oacc[2 * dg],     pah[kc], &vH[0]);
                    mma_bf16(oacc[2 * dg + 1], pah[kc], &vH[2]);
                    mma_bf16(oacc[2 * dg],     pah[kc], &vL[0]);
                    mma_bf16(oacc[2 * dg + 1], pah[kc], &vL[2]);
                    mma_bf16(oacc[2 * dg],     pal[kc], &vH[0]);
                    mma_bf16(oacc[2 * dg + 1], pal[kc], &vH[2]);
                }
            }
        }
        __syncthreads();
    }

    // ---- epilogue ----
    const float inv0 = 1.f / l0, inv1 = 1.f / l1;
    const int r0 = wbase + (lane >> 2);
    const int colb = h * HDIM + 2 * (lane & 3);
    const size_t ro0 = (size_t)(b_ * SEQ + r0) * HID + colb;
    const size_t ro1 = ro0 + (size_t)8 * HID;
#pragma unroll
    for (int g = 0; g < 8; ++g) {
        uint32_t hi, lo;
        split2(oacc[g][0] * inv0, oacc[g][1] * inv0, hi, lo);
        *(uint32_t*)(g_chi + ro0 + 8 * g) = hi;
        *(uint32_t*)(g_clo + ro0 + 8 * g) = lo;
        split2(oacc[g][2] * inv1, oacc[g][3] * inv1, hi, lo);
        *(uint32_t*)(g_chi + ro1 + 8 * g) = hi;
        *(uint32_t*)(g_clo + ro1 + 8 * g) = lo;
    }
}

// ---------------------------------------------------------------------------
extern "C" void kernel_launch(void* const* d_in, const int* in_sizes, int n_in,
                              void* d_out, int out_size)
{
    const float* X    = (const float*)d_in[0];
    const int*   pos  = (const int*)  d_in[2];
    const float* cosb = (const float*)d_in[3];
    const float* sinb = (const float*)d_in[4];
    const float* Wq   = (const float*)d_in[5];
    const float* Wk   = (const float*)d_in[6];
    const float* Wv   = (const float*)d_in[7];
    const float* Wo   = (const float*)d_in[8];
    float* out = (float*)d_out;

    static int attr_done = 0;
    if (!attr_done) {
        cudaFuncSetAttribute(hgemm_kernel, cudaFuncAttributeMaxDynamicSharedMemorySize,
                             2 * 4 * TILEB);
        cudaFuncSetAttribute(attn_kernel, cudaFuncAttributeMaxDynamicSharedMemorySize,
                             2 * 4 * KT_);
        attr_done = 1;
    }

    __nv_bfloat16 *xhi, *xlo, *chi, *clo;
    cudaGetSymbolAddress((void**)&xhi, g_xhi);
    cudaGetSymbolAddress((void**)&xlo, g_xlo);
    cudaGetSymbolAddress((void**)&chi, g_chi);
    cudaGetSymbolAddress((void**)&clo, g_clo);

    // 1) convert inputs to bf16 hi/lo
    {
        int n8 = BATCH * SEQ * HID / 8;
        split_rows_kernel<<<(n8 + 255) / 256, 256>>>(X, xhi, xlo, n8);
        dim3 gw(HID / 32, HID / 32, 4);
        split_wT_kernel<<<gw, dim3(32, 8)>>>(Wq, Wk, Wv, Wo);
    }
    // 2) QKV projection + RoPE (HMMA, pipelined)
    {
        dim3 g(HID / 128, (BATCH * SEQ) / 128, 3);
        hgemm_kernel<<<g, 256, 2 * 4 * TILEB>>>(xhi, xlo, 0, pos, cosb, sinb, nullptr);
    }
    // 3) attention (HMMA flash, pipelined, 2 CTAs/SM)
    {
        dim3 g(SEQ / 128, NHEAD, BATCH);
        attn_kernel<<<g, 256, 2 * 4 * KT_>>>();
    }
    // 4) output projection (HMMA, pipelined)
    {
        dim3 g(HID / 128, (BATCH * SEQ) / 128, 1);
        hgemm_kernel<<<g, 256, 2 * 4 * TILEB>>>(chi, clo, 1, pos, cosb, sinb, out);
    }
}

// round 8
// speedup vs baseline: 1.0378x; 1.0378x over previous
#include <cuda_runtime.h>
#include <cuda_bf16.h>
#include <cstdint>

#define BATCH 2
#define SEQ   2048
#define HID   1024
#define NHEAD 16
#define HDIM  64
#define SCALE 0.125f

// ---------------- device scratch (static allocations only) ----------------
__device__ __nv_bfloat16 g_xhi[BATCH * SEQ * HID];
__device__ __nv_bfloat16 g_xlo[BATCH * SEQ * HID];
__device__ __nv_bfloat16 g_whi[4 * HID * HID];   // transposed [N][K], mats q,k,v,o
__device__ __nv_bfloat16 g_wlo[4 * HID * HID];
__device__ __nv_bfloat16 g_chi[BATCH * SEQ * HID];
__device__ __nv_bfloat16 g_clo[BATCH * SEQ * HID];
__device__ __nv_bfloat16 g_qhi[BATCH * NHEAD * SEQ * HDIM];
__device__ __nv_bfloat16 g_qlo[BATCH * NHEAD * SEQ * HDIM];
__device__ __nv_bfloat16 g_khi[BATCH * NHEAD * SEQ * HDIM];
__device__ __nv_bfloat16 g_klo[BATCH * NHEAD * SEQ * HDIM];
__device__ __nv_bfloat16 g_vhi[BATCH * NHEAD * SEQ * HDIM];
__device__ __nv_bfloat16 g_vlo[BATCH * NHEAD * SEQ * HDIM];

// ---------------- helpers ----------------
__device__ __forceinline__ uint32_t smem_u32(const void* p) {
    uint32_t a;
    asm("{ .reg .u64 t; cvta.to.shared.u64 t, %1; cvt.u32.u64 %0, t; }" : "=r"(a) : "l"(p));
    return a;
}
__device__ __forceinline__ void ldsm_x4(uint32_t* r, uint32_t addr) {
    asm volatile("ldmatrix.sync.aligned.m8n8.x4.shared.b16 {%0,%1,%2,%3}, [%4];"
                 : "=r"(r[0]), "=r"(r[1]), "=r"(r[2]), "=r"(r[3]) : "r"(addr));
}
__device__ __forceinline__ void ldsm_x4_t(uint32_t* r, uint32_t addr) {
    asm volatile("ldmatrix.sync.aligned.m8n8.x4.trans.shared.b16 {%0,%1,%2,%3}, [%4];"
                 : "=r"(r[0]), "=r"(r[1]), "=r"(r[2]), "=r"(r[3]) : "r"(addr));
}
__device__ __forceinline__ void mma_bf16(float* c, const uint32_t* a, const uint32_t* b) {
    asm volatile(
        "mma.sync.aligned.m16n8k16.row.col.f32.bf16.bf16.f32 "
        "{%0,%1,%2,%3},{%4,%5,%6,%7},{%8,%9},{%0,%1,%2,%3};"
        : "+f"(c[0]), "+f"(c[1]), "+f"(c[2]), "+f"(c[3])
        : "r"(a[0]), "r"(a[1]), "r"(a[2]), "r"(a[3]), "r"(b[0]), "r"(b[1]));
}
__device__ __forceinline__ void split2(float a, float b, uint32_t& hi, uint32_t& lo) {
    __nv_bfloat162 h = __floats2bfloat162_rn(a, b);
    float2 hf = __bfloat1622float2(h);
    __nv_bfloat162 l = __floats2bfloat162_rn(a - hf.x, b - hf.y);
    hi = *(uint32_t*)&h;
    lo = *(uint32_t*)&l;
}
__device__ __forceinline__ void cp16(uint32_t dst, const void* src) {
    asm volatile("cp.async.cg.shared.global [%0], [%1], 16;" :: "r"(dst), "l"(src));
}
#define CP_COMMIT() asm volatile("cp.async.commit_group;" ::: "memory")
#define CP_WAIT0()  asm volatile("cp.async.wait_group 0;" ::: "memory")
#define CP_WAIT1()  asm volatile("cp.async.wait_group 1;" ::: "memory")

// ---------------- convert kernels ----------------
union BPack { __nv_bfloat16 b[8]; uint4 v; };

__global__ void split_rows_kernel(const float* __restrict__ in,
                                  __nv_bfloat16* __restrict__ hi,
                                  __nv_bfloat16* __restrict__ lo, int n8) {
    int i = blockIdx.x * blockDim.x + threadIdx.x;
    if (i >= n8) return;
    float f[8];
    *(float4*)(f)     = ((const float4*)in)[i * 2];
    *(float4*)(f + 4) = ((const float4*)in)[i * 2 + 1];
    BPack h, l;
#pragma unroll
    for (int j = 0; j < 8; ++j) {
        h.b[j] = __float2bfloat16(f[j]);
        l.b[j] = __float2bfloat16(f[j] - __bfloat162float(h.b[j]));
    }
    ((uint4*)hi)[i] = h.v;
    ((uint4*)lo)[i] = l.v;
}

__global__ void split_wT_kernel(const float* __restrict__ Wq, const float* __restrict__ Wk,
                                const float* __restrict__ Wv, const float* __restrict__ Wo) {
    __shared__ float t[32][33];
    const int mat = blockIdx.z;
    const float* W = (mat == 0) ? Wq : (mat == 1) ? Wk : (mat == 2) ? Wv : Wo;
    __nv_bfloat16* hi = g_whi + (size_t)mat * HID * HID;
    __nv_bfloat16* lo = g_wlo + (size_t)mat * HID * HID;
    const int n0 = blockIdx.x * 32, k0 = blockIdx.y * 32;
    const int tx = threadIdx.x, ty = threadIdx.y;
#pragma unroll
    for (int i = 0; i < 4; ++i)
        t[ty + 8 * i][tx] = W[(size_t)(k0 + ty + 8 * i) * HID + n0 + tx];
    __syncthreads();
#pragma unroll
    for (int i = 0; i < 4; ++i) {
        float v = t[tx][ty + 8 * i];
        __nv_bfloat16 h = __float2bfloat16(v);
        size_t idx = (size_t)(n0 + ty + 8 * i) * HID + k0 + tx;
        hi[idx] = h;
        lo[idx] = __float2bfloat16(v - __bfloat162float(h));
    }
}

// ---------------------------------------------------------------------------
// HMMA bf16 split GEMM, 2-stage cp.async pipeline (unchanged from R6).
// ---------------------------------------------------------------------------
#define TILEB 10240   // 128 rows * 80 bytes

__global__ __launch_bounds__(256, 2) void hgemm_kernel(
    const __nv_bfloat16* __restrict__ Ahi, const __nv_bfloat16* __restrict__ Alo,
    int mode, const int* __restrict__ pos_ids,
    const float* __restrict__ cosb, const float* __restrict__ sinb,
    float* __restrict__ outp)
{
    extern __shared__ char dsm[];
    const uint32_t S0 = smem_u32(dsm);

    const int tid = threadIdx.x;
    const int lane = tid & 31, wid = tid >> 5;
    const int wm = wid & 3, wn = wid >> 2;
    const int z = blockIdx.z;
    const int row0 = blockIdx.y << 7, col0 = blockIdx.x << 7;
    const int wsel = (mode == 0) ? z : 3;
    const __nv_bfloat16* Bhi = g_whi + (size_t)wsel * HID * HID;
    const __nv_bfloat16* Blo = g_wlo + (size_t)wsel * HID * HID;

    float acc[2][8][4];
#pragma unroll
    for (int t = 0; t < 2; ++t)
#pragma unroll
        for (int j = 0; j < 8; ++j)
#pragma unroll
            for (int e = 0; e < 4; ++e) acc[t][j][e] = 0.f;

    const int lrow = tid >> 1;
    const int lch  = (tid & 1) * 2;
    const uint32_t s_off = lrow * 80 + lch * 16;

    const int a_row = wm * 32 + (lane & 15);
    const int a_ch  = lane >> 4;
    const int b_row = wn * 64 + (lane & 7) + ((lane & 16) >> 1);
    const int b_ch  = (lane >> 3) & 1;

    auto stage_load = [&](int it, int s) {
        const int k0 = it * 32;
        const size_t ga = (size_t)(row0 + lrow) * HID + k0 + lch * 8;
        const size_t gb = (size_t)(col0 + lrow) * HID + k0 + lch * 8;
        const uint32_t d = S0 + s * (4 * TILEB) + s_off;
        cp16(d,                 Ahi + ga); cp16(d + 16,             Ahi + ga + 8);
        cp16(d + TILEB,         Alo + ga); cp16(d + TILEB + 16,     Alo + ga + 8);
        cp16(d + 2 * TILEB,     Bhi + gb); cp16(d + 2 * TILEB + 16, Bhi + gb + 8);
        cp16(d + 3 * TILEB,     Blo + gb); cp16(d + 3 * TILEB + 16, Blo + gb + 8);
    };

    stage_load(0, 0);
    CP_COMMIT();

    for (int it = 0; it < HID / 32; ++it) {
        const int s = it & 1;
        if (it + 1 < HID / 32) {
            stage_load(it + 1, s ^ 1);
            CP_COMMIT();
            CP_WAIT1();
        } else {
            CP_WAIT0();
        }
        __syncthreads();

        const uint32_t uAh = S0 + s * (4 * TILEB);
        const uint32_t uAl = uAh + TILEB;
        const uint32_t uBh = uAh + 2 * TILEB;
        const uint32_t uBl = uAh + 3 * TILEB;
#pragma unroll
        for (int kh = 0; kh < 2; ++kh) {
            uint32_t aH[2][4], aL[2][4], bH[4][4], bL[4][4];
            const uint32_t a_off = a_row * 80 + (kh * 2 + a_ch) * 16;
            const uint32_t b_off = b_row * 80 + (kh * 2 + b_ch) * 16;
            ldsm_x4(aH[0], uAh + a_off);
            ldsm_x4(aH[1], uAh + a_off + 16 * 80);
            ldsm_x4(aL[0], uAl + a_off);
            ldsm_x4(aL[1], uAl + a_off + 16 * 80);
#pragma unroll
            for (int g = 0; g < 4; ++g) {
                ldsm_x4(bH[g], uBh + b_off + g * (16 * 80));
                ldsm_x4(bL[g], uBl + b_off + g * (16 * 80));
            }
#pragma unroll
            for (int t = 0; t < 2; ++t)
#pragma unroll
                for (int g = 0; g < 4; ++g) {
                    mma_bf16(acc[t][2 * g],     aH[t], &bH[g][0]);
                    mma_bf16(acc[t][2 * g + 1], aH[t], &bH[g][2]);
                }
#pragma unroll
            for (int t = 0; t < 2; ++t)
#pragma unroll
                for (int g = 0; g < 4; ++g) {
                    mma_bf16(acc[t][2 * g],     aH[t], &bL[g][0]);
                    mma_bf16(acc[t][2 * g + 1], aH[t], &bL[g][2]);
                }
#pragma unroll
            for (int t = 0; t < 2; ++t)
#pragma unroll
                for (int g = 0; g < 4; ++g) {
                    mma_bf16(acc[t][2 * g],     aL[t], &bH[g][0]);
                    mma_bf16(acc[t][2 * g + 1], aL[t], &bH[g][2]);
                }
        }
        __syncthreads();
    }

    // ---------------- epilogue ----------------
    const int q2 = (lane & 3) * 2;
#pragma unroll
    for (int t = 0; t < 2; ++t) {
#pragma unroll
        for (int h2 = 0; h2 < 2; ++h2) {
            const int row = row0 + wm * 32 + t * 16 + (lane >> 2) + h2 * 8;
            if (mode == 1) {
                float* dst = outp + (size_t)row * HID + col0 + wn * 64 + q2;
#pragma unroll
                for (int j = 0; j < 8; ++j)
                    *(float2*)(dst + j * 8) =
                        make_float2(acc[t][j][h2 * 2], acc[t][j][h2 * 2 + 1]);
            } else {
                const int b_ = row >> 11, s_ = row & (SEQ - 1);
                const int h = (col0 >> 6) + wn;
                const size_t base = ((size_t)(b_ * NHEAD + h) * SEQ + s_) * HDIM;
                if (z == 2) {
#pragma unroll
                    for (int j = 0; j < 8; ++j) {
                        uint32_t hi, lo;
                        split2(acc[t][j][h2 * 2], acc[t][j][h2 * 2 + 1], hi, lo);
                        *(uint32_t*)(g_vhi + base + j * 8 + q2) = hi;
                        *(uint32_t*)(g_vlo + base + j * 8 + q2) = lo;
                    }
                } else {
                    const int pos = pos_ids[b_ * SEQ + s_];
                    const float* cr = cosb + pos * HDIM;
                    const float* sr = sinb + pos * HDIM;
                    __nv_bfloat16* dhi = (z == 0) ? g_qhi : g_khi;
                    __nv_bfloat16* dlo = (z == 0) ? g_qlo : g_klo;
                    const float sc_ = (z == 0) ? SCALE : 1.0f;
#pragma unroll
                    for (int j = 0; j < 4; ++j) {
                        float o1[2], o2[2];
#pragma unroll
                        for (int e = 0; e < 2; ++e) {
                            const int d = j * 8 + q2 + e;
                            const float x = acc[t][j][h2 * 2 + e];
                            const float y = acc[t][j + 4][h2 * 2 + e];
                            o1[e] = (x * cr[d] - y * sr[d]) * sc_;
                            o2[e] = (y * cr[d + 32] + x * sr[d + 32]) * sc_;
                        }
                        uint32_t hi, lo;
                        split2(o1[0], o1[1], hi, lo);
                        *(uint32_t*)(dhi + base + j * 8 + q2) = hi;
                        *(uint32_t*)(dlo + base + j * 8 + q2) = lo;
                        split2(o2[0], o2[1], hi, lo);
                        *(uint32_t*)(dhi + base + j * 8 + q2 + 32) = hi;
                        *(uint32_t*)(dlo + base + j * 8 + q2 + 32) = lo;
                    }
                }
            }
        }
    }
}

// ---------------------------------------------------------------------------
// HMMA flash attention: 4-buffer cp.async ring, depth-2 prefetch, and S(kt+1)
// computed DURING softmax(kt)/PV(kt) so the tensor pipe never drains.
// One __syncthreads per iteration (4 buffers bound warp skew to <1 iter).
// ---------------------------------------------------------------------------
#define AP  144    // bytes per smem row (64 bf16 + pad)
#define KT_ 9216   // 64 rows * AP
#define NBUF 4

__global__ __launch_bounds__(256) void attn_kernel()
{
    extern __shared__ char dsm[];
    const uint32_t S0 = smem_u32(dsm);

    const int tid = threadIdx.x, lane = tid & 31, wid = tid >> 5;
    const int qi = gridDim.x - 1 - blockIdx.x;
    const int h = blockIdx.y, b_ = blockIdx.z;
    const int q0 = qi << 7;
    const size_t hb = (size_t)(b_ * NHEAD + h) * SEQ * HDIM;
    const __nv_bfloat16 *qhi = g_qhi + hb, *qlo = g_qlo + hb;
    const __nv_bfloat16 *khi = g_khi + hb, *klo = g_klo + hb;
    const __nv_bfloat16 *vhi = g_vhi + hb, *vlo = g_vlo + hb;

    // ---- stage Q into buffer region 0/1 via cp.async ----
    {
        const int r = tid >> 1, half = tid & 1;
        const __nv_bfloat16* sh = qhi + (size_t)(q0 + r) * HDIM + half * 32;
        const __nv_bfloat16* sl = qlo + (size_t)(q0 + r) * HDIM + half * 32;
        const uint32_t dh = S0 + ((r < 64) ? 0 : 2 * KT_) + (r & 63) * AP + half * 64;
        const uint32_t dl = dh + KT_;
#pragma unroll
        for (int c = 0; c < 4; ++c) {
            cp16(dh + c * 16, sh + c * 8);
            cp16(dl + c * 16, sl + c * 8);
        }
    }
    CP_COMMIT();
    CP_WAIT0();
    __syncthreads();

    // ---- Q fragments ----
    uint32_t qfh[4][4], qfl[4][4];
    {
        const uint32_t bh = S0 + ((wid < 4) ? 0 : 2 * KT_);
        const uint32_t bl = bh + KT_;
        const int arow = (wid & 3) * 16 + (lane & 15);
        const int ach = lane >> 4;
#pragma unroll
        for (int kc = 0; kc < 4; ++kc) {
            const uint32_t off = arow * AP + (kc * 2 + ach) * 16;
            ldsm_x4(qfh[kc], bh + off);
            ldsm_x4(qfl[kc], bl + off);
        }
    }
    __syncthreads();   // everyone done reading Q before KV overwrites

    float oacc[8][4];
#pragma unroll
    for (int g = 0; g < 8; ++g)
#pragma unroll
        for (int e = 0; e < 4; ++e) oacc[g][e] = 0.f;
    float m0 = -1e30f, m1 = -1e30f, l0 = 0.f, l1 = 0.f;

    const int wbase = q0 + wid * 16;
    const int nt = (q0 >> 6) + 2;
    const int lrow = tid >> 2, lq = tid & 3;
    const int brow_ = (lane & 7) + ((lane & 16) >> 1);
    const int bch_ = (lane >> 3) & 1;
    const int vrow_ = lane & 15;
    const int vcol_ = (lane & 16) ? 8 : 0;

    auto kv_load = [&](int kt) {
        const int k0 = kt << 6;
        const size_t src = (size_t)(k0 + lrow) * HDIM + lq * 16;
        const uint32_t d = S0 + (kt & (NBUF - 1)) * (4 * KT_) + lrow * AP + lq * 32;
        cp16(d,                khi + src); cp16(d + 16,            khi + src + 8);
        cp16(d + KT_,          klo + src); cp16(d + KT_ + 16,      klo + src + 8);
        cp16(d + 2 * KT_,      vhi + src); cp16(d + 2 * KT_ + 16,  vhi + src + 8);
        cp16(d + 3 * KT_,      vlo + src); cp16(d + 3 * KT_ + 16,  vlo + src + 8);
    };

    // S = Q K^T for tile kt into sc
    auto qk = [&](float (&sc)[8][4], int kt) {
        const uint32_t uKh = S0 + (kt & (NBUF - 1)) * (4 * KT_);
        const uint32_t uKl = uKh + KT_;
#pragma unroll
        for (int g = 0; g < 8; ++g)
#pragma unroll
            for (int e = 0; e < 4; ++e) sc[g][e] = 0.f;
#pragma unroll
        for (int kc = 0; kc < 4; ++kc) {
#pragma unroll
            for (int g = 0; g < 4; ++g) {
                uint32_t bH[4], bL[4];
                const uint32_t boff = (g * 16 + brow_) * AP + (kc * 2 + bch_) * 16;
                ldsm_x4(bH, uKh + boff);
                ldsm_x4(bL, uKl + boff);
                mma_bf16(sc[2 * g],     qfh[kc], &bH[0]);
                mma_bf16(sc[2 * g + 1], qfh[kc], &bH[2]);
                mma_bf16(sc[2 * g],     qfh[kc], &bL[0]);
                mma_bf16(sc[2 * g + 1], qfh[kc], &bL[2]);
                mma_bf16(sc[2 * g],     qfl[kc], &bH[0]);
                mma_bf16(sc[2 * g + 1], qfl[kc], &bH[2]);
            }
        }
    };

    // softmax(cur) + O += P V for tile kt
    auto smax_pv = [&](float (&sc)[8][4], int kt) {
        const int k0 = kt << 6;
        const int r0 = wbase + (lane >> 2), r1 = r0 + 8;
        if (k0 + 63 > wbase) {
#pragma unroll
            for (int g = 0; g < 8; ++g) {
#pragma unroll
                for (int e = 0; e < 2; ++e) {
                    const int col = k0 + 8 * g + 2 * (lane & 3) + e;
                    if (col > r0) sc[g][e] = -1e9f;
                    if (col > r1) sc[g][2 + e] = -1e9f;
                }
            }
        }
        float mx0 = sc[0][0], mx1 = sc[0][2];
#pragma unroll
        for (int g = 0; g < 8; ++g) {
            mx0 = fmaxf(mx0, fmaxf(sc[g][0], sc[g][1]));
            mx1 = fmaxf(mx1, fmaxf(sc[g][2], sc[g][3]));
        }
        mx0 = fmaxf(mx0, __shfl_xor_sync(0xffffffffu, mx0, 1));
        mx0 = fmaxf(mx0, __shfl_xor_sync(0xffffffffu, mx0, 2));
        mx1 = fmaxf(mx1, __shfl_xor_sync(0xffffffffu, mx1, 1));
        mx1 = fmaxf(mx1, __shfl_xor_sync(0xffffffffu, mx1, 2));
        const float nm0 = fmaxf(m0, mx0), nm1 = fmaxf(m1, mx1);
        const float cr0 = __expf(m0 - nm0), cr1 = __expf(m1 - nm1);
        m0 = nm0; m1 = nm1;
        float rs0 = 0.f, rs1 = 0.f;
#pragma unroll
        for (int g = 0; g < 8; ++g) {
            sc[g][0] = __expf(sc[g][0] - nm0);
            sc[g][1] = __expf(sc[g][1] - nm0);
            sc[g][2] = __expf(sc[g][2] - nm1);
            sc[g][3] = __expf(sc[g][3] - nm1);
            rs0 += sc[g][0] + sc[g][1];
            rs1 += sc[g][2] + sc[g][3];
        }
        rs0 += __shfl_xor_sync(0xffffffffu, rs0, 1);
        rs0 += __shfl_xor_sync(0xffffffffu, rs0, 2);
        rs1 += __shfl_xor_sync(0xffffffffu, rs1, 1);
        rs1 += __shfl_xor_sync(0xffffffffu, rs1, 2);
        l0 = l0 * cr0 + rs0;
        l1 = l1 * cr1 + rs1;
#pragma unroll
        for (int g = 0; g < 8; ++g) {
            oacc[g][0] *= cr0; oacc[g][1] *= cr0;
            oacc[g][2] *= cr1; oacc[g][3] *= cr1;
        }
        uint32_t pah[4][4], pal[4][4];
#pragma unroll
        for (int kc = 0; kc < 4; ++kc) {
            split2(sc[2 * kc][0],     sc[2 * kc][1],     pah[kc][0], pal[kc][0]);
            split2(sc[2 * kc][2],     sc[2 * kc][3],     pah[kc][1], pal[kc][1]);
            split2(sc[2 * kc + 1][0], sc[2 * kc + 1][1], pah[kc][2], pal[kc][2]);
            split2(sc[2 * kc + 1][2], sc[2 * kc + 1][3], pah[kc][3], pal[kc][3]);
        }
        const uint32_t uVh = S0 + (kt & (NBUF - 1)) * (4 * KT_) + 2 * KT_;
        const uint32_t uVl = uVh + KT_;
#pragma unroll
        for (int kc = 0; kc < 4; ++kc) {
#pragma unroll
            for (int dg = 0; dg < 4; ++dg) {
                uint32_t vH[4], vL[4];
                const uint32_t voff = (kc * 16 + vrow_) * AP + (dg * 16 + vcol_) * 2;
                ldsm_x4_t(vH, uVh + voff);
                ldsm_x4_t(vL, uVl + voff);
                mma_bf16(oacc[2 * dg],     pah[kc], &vH[0]);
                mma_bf16(oacc[2 * dg + 1], pah[kc], &vH[2]);
                mma_bf16(oacc[2 * dg],     pah[kc], &vL[0]);
                mma_bf16(oacc[2 * dg + 1], pah[kc], &vL[2]);
                mma_bf16(oacc[2 * dg],     pal[kc], &vH[0]);
                mma_bf16(oacc[2 * dg + 1], pal[kc], &vH[2]);
            }
        }
    };

    // one pipeline iteration: cur holds S(kt); prefetch S(kt+1) into nxt,
    // overlapped with softmax(kt)+PV(kt).
    auto iter = [&](float (&cur)[8][4], float (&nxt)[8][4], int kt) {
        if (kt + 2 < nt) kv_load(kt + 2);
        CP_COMMIT();                       // uniform group numbering
        CP_WAIT1();                        // G(kt+1) complete
        __syncthreads();
        const bool act  = (kt << 6) <= wbase + 15;
        const bool nact = (kt + 1 < nt) && (((kt + 1) << 6) <= wbase + 15);
        if (nact) qk(nxt, kt + 1);         // tensor work, independent of cur
        if (act)  smax_pv(cur, kt);        // softmax overlaps qk's HMMAs
    };

    // ---- prologue ----
    float scA[8][4], scB[8][4];
    kv_load(0);
    CP_COMMIT();
    if (nt > 1) kv_load(1);
    CP_COMMIT();
    CP_WAIT1();                            // KV(0) ready
    __syncthreads();
    qk(scA, 0);

    for (int kt = 0; kt < nt; ) {
        iter(scA, scB, kt); ++kt;
        if (kt < nt) { iter(scB, scA, kt); ++kt; }
    }

    // ---- epilogue ----
    const float inv0 = 1.f / l0, inv1 = 1.f / l1;
    const int r0 = wbase + (lane >> 2);
    const int colb = h * HDIM + 2 * (lane & 3);
    const size_t ro0 = (size_t)(b_ * SEQ + r0) * HID + colb;
    const size_t ro1 = ro0 + (size_t)8 * HID;
#pragma unroll
    for (int g = 0; g < 8; ++g) {
        uint32_t hi, lo;
        split2(oacc[g][0] * inv0, oacc[g][1] * inv0, hi, lo);
        *(uint32_t*)(g_chi + ro0 + 8 * g) = hi;
        *(uint32_t*)(g_clo + ro0 + 8 * g) = lo;
        split2(oacc[g][2] * inv1, oacc[g][3] * inv1, hi, lo);
        *(uint32_t*)(g_chi + ro1 + 8 * g) = hi;
        *(uint32_t*)(g_clo + ro1 + 8 * g) = lo;
    }
}

// ---------------------------------------------------------------------------
extern "C" void kernel_launch(void* const* d_in, const int* in_sizes, int n_in,
                              void* d_out, int out_size)
{
    const float* X    = (const float*)d_in[0];
    const int*   pos  = (const int*)  d_in[2];
    const float* cosb = (const float*)d_in[3];
    const float* sinb = (const float*)d_in[4];
    const float* Wq   = (const float*)d_in[5];
    const float* Wk   = (const float*)d_in[6];
    const float* Wv   = (const float*)d_in[7];
    const float* Wo   = (const float*)d_in[8];
    float* out = (float*)d_out;

    static int attr_done = 0;
    if (!attr_done) {
        cudaFuncSetAttribute(hgemm_kernel, cudaFuncAttributeMaxDynamicSharedMemorySize,
                             2 * 4 * TILEB);
        cudaFuncSetAttribute(attn_kernel, cudaFuncAttributeMaxDynamicSharedMemorySize,
                             NBUF * 4 * KT_);
        attr_done = 1;
    }

    __nv_bfloat16 *xhi, *xlo, *chi, *clo;
    cudaGetSymbolAddress((void**)&xhi, g_xhi);
    cudaGetSymbolAddress((void**)&xlo, g_xlo);
    cudaGetSymbolAddress((void**)&chi, g_chi);
    cudaGetSymbolAddress((void**)&clo, g_clo);

    // 1) convert inputs to bf16 hi/lo
    {
        int n8 = BATCH * SEQ * HID / 8;
        split_rows_kernel<<<(n8 + 255) / 256, 256>>>(X, xhi, xlo, n8);
        dim3 gw(HID / 32, HID / 32, 4);
        split_wT_kernel<<<gw, dim3(32, 8)>>>(Wq, Wk, Wv, Wo);
    }
    // 2) QKV projection + RoPE (HMMA, pipelined)
    {
        dim3 g(HID / 128, (BATCH * SEQ) / 128, 3);
        hgemm_kernel<<<g, 256, 2 * 4 * TILEB>>>(xhi, xlo, 0, pos, cosb, sinb, nullptr);
    }
    // 3) attention (HMMA flash, S-prefetch pipelined)
    {
        dim3 g(SEQ / 128, NHEAD, BATCH);
        attn_kernel<<<g, 256, NBUF * 4 * KT_>>>();
    }
    // 4) output projection (HMMA, pipelined)
    {
        dim3 g(HID / 128, (BATCH * SEQ) / 128, 1);
        hgemm_kernel<<<g, 256, 2 * 4 * TILEB>>>(chi, clo, 1, pos, cosb, sinb, out);
    }
}

// round 9
// speedup vs baseline: 1.2410x; 1.1959x over previous
#include <cuda_runtime.h>
#include <cuda_bf16.h>
#include <cuda_fp16.h>
#include <cstdint>

#define BATCH 2
#define SEQ   2048
#define HID   1024
#define NHEAD 16
#define HDIM  64
#define SCALE 0.125f

// ---------------- device scratch (static allocations only) ----------------
__device__ __nv_bfloat16 g_xhi[BATCH * SEQ * HID];
__device__ __nv_bfloat16 g_xlo[BATCH * SEQ * HID];
__device__ __nv_bfloat16 g_whi[4 * HID * HID];   // transposed [N][K], mats q,k,v,o
__device__ __nv_bfloat16 g_wlo[4 * HID * HID];
__device__ __nv_bfloat16 g_chi[BATCH * SEQ * HID];
__device__ __nv_bfloat16 g_clo[BATCH * SEQ * HID];
__device__ __half g_qh[BATCH * NHEAD * SEQ * HDIM];
__device__ __half g_kh[BATCH * NHEAD * SEQ * HDIM];
__device__ __half g_vh[BATCH * NHEAD * SEQ * HDIM];

// ---------------- helpers ----------------
__device__ __forceinline__ uint32_t smem_u32(const void* p) {
    uint32_t a;
    asm("{ .reg .u64 t; cvta.to.shared.u64 t, %1; cvt.u32.u64 %0, t; }" : "=r"(a) : "l"(p));
    return a;
}
__device__ __forceinline__ void ldsm_x4(uint32_t* r, uint32_t addr) {
    asm volatile("ldmatrix.sync.aligned.m8n8.x4.shared.b16 {%0,%1,%2,%3}, [%4];"
                 : "=r"(r[0]), "=r"(r[1]), "=r"(r[2]), "=r"(r[3]) : "r"(addr));
}
__device__ __forceinline__ void ldsm_x4_t(uint32_t* r, uint32_t addr) {
    asm volatile("ldmatrix.sync.aligned.m8n8.x4.trans.shared.b16 {%0,%1,%2,%3}, [%4];"
                 : "=r"(r[0]), "=r"(r[1]), "=r"(r[2]), "=r"(r[3]) : "r"(addr));
}
__device__ __forceinline__ void mma_bf16(float* c, const uint32_t* a, const uint32_t* b) {
    asm volatile(
        "mma.sync.aligned.m16n8k16.row.col.f32.bf16.bf16.f32 "
        "{%0,%1,%2,%3},{%4,%5,%6,%7},{%8,%9},{%0,%1,%2,%3};"
        : "+f"(c[0]), "+f"(c[1]), "+f"(c[2]), "+f"(c[3])
        : "r"(a[0]), "r"(a[1]), "r"(a[2]), "r"(a[3]), "r"(b[0]), "r"(b[1]));
}
__device__ __forceinline__ void mma_f16(float* c, const uint32_t* a, const uint32_t* b) {
    asm volatile(
        "mma.sync.aligned.m16n8k16.row.col.f32.f16.f16.f32 "
        "{%0,%1,%2,%3},{%4,%5,%6,%7},{%8,%9},{%0,%1,%2,%3};"
        : "+f"(c[0]), "+f"(c[1]), "+f"(c[2]), "+f"(c[3])
        : "r"(a[0]), "r"(a[1]), "r"(a[2]), "r"(a[3]), "r"(b[0]), "r"(b[1]));
}
__device__ __forceinline__ void split2(float a, float b, uint32_t& hi, uint32_t& lo) {
    __nv_bfloat162 h = __floats2bfloat162_rn(a, b);
    float2 hf = __bfloat1622float2(h);
    __nv_bfloat162 l = __floats2bfloat162_rn(a - hf.x, b - hf.y);
    hi = *(uint32_t*)&h;
    lo = *(uint32_t*)&l;
}
__device__ __forceinline__ uint32_t packh2(float a, float b) {
    __half2 h = __floats2half2_rn(a, b);
    return *(uint32_t*)&h;
}
__device__ __forceinline__ void cp16(uint32_t dst, const void* src) {
    asm volatile("cp.async.cg.shared.global [%0], [%1], 16;" :: "r"(dst), "l"(src));
}
#define CP_COMMIT() asm volatile("cp.async.commit_group;" ::: "memory")
#define CP_WAIT0()  asm volatile("cp.async.wait_group 0;" ::: "memory")
#define CP_WAIT1()  asm volatile("cp.async.wait_group 1;" ::: "memory")

// ---------------- convert kernels ----------------
union BPack { __nv_bfloat16 b[8]; uint4 v; };

__global__ void split_rows_kernel(const float* __restrict__ in,
                                  __nv_bfloat16* __restrict__ hi,
                                  __nv_bfloat16* __restrict__ lo, int n8) {
    int i = blockIdx.x * blockDim.x + threadIdx.x;
    if (i >= n8) return;
    float f[8];
    *(float4*)(f)     = ((const float4*)in)[i * 2];
    *(float4*)(f + 4) = ((const float4*)in)[i * 2 + 1];
    BPack h, l;
#pragma unroll
    for (int j = 0; j < 8; ++j) {
        h.b[j] = __float2bfloat16(f[j]);
        l.b[j] = __float2bfloat16(f[j] - __bfloat162float(h.b[j]));
    }
    ((uint4*)hi)[i] = h.v;
    ((uint4*)lo)[i] = l.v;
}

__global__ void split_wT_kernel(const float* __restrict__ Wq, const float* __restrict__ Wk,
                                const float* __restrict__ Wv, const float* __restrict__ Wo) {
    __shared__ float t[32][33];
    const int mat = blockIdx.z;
    const float* W = (mat == 0) ? Wq : (mat == 1) ? Wk : (mat == 2) ? Wv : Wo;
    __nv_bfloat16* hi = g_whi + (size_t)mat * HID * HID;
    __nv_bfloat16* lo = g_wlo + (size_t)mat * HID * HID;
    const int n0 = blockIdx.x * 32, k0 = blockIdx.y * 32;
    const int tx = threadIdx.x, ty = threadIdx.y;
#pragma unroll
    for (int i = 0; i < 4; ++i)
        t[ty + 8 * i][tx] = W[(size_t)(k0 + ty + 8 * i) * HID + n0 + tx];
    __syncthreads();
#pragma unroll
    for (int i = 0; i < 4; ++i) {
        float v = t[tx][ty + 8 * i];
        __nv_bfloat16 h = __float2bfloat16(v);
        size_t idx = (size_t)(n0 + ty + 8 * i) * HID + k0 + tx;
        hi[idx] = h;
        lo[idx] = __float2bfloat16(v - __bfloat162float(h));
    }
}

// ---------------------------------------------------------------------------
// HMMA bf16 split GEMM, 2-stage cp.async pipeline.
// mode 0: QKV + RoPE -> fp16 Q,K,V (Q pre-scaled). mode 1: out-proj -> fp32.
// ---------------------------------------------------------------------------
#define TILEB 10240   // 128 rows * 80 bytes

__global__ __launch_bounds__(256, 2) void hgemm_kernel(
    const __nv_bfloat16* __restrict__ Ahi, const __nv_bfloat16* __restrict__ Alo,
    int mode, const int* __restrict__ pos_ids,
    const float* __restrict__ cosb, const float* __restrict__ sinb,
    float* __restrict__ outp)
{
    extern __shared__ char dsm[];
    const uint32_t S0 = smem_u32(dsm);

    const int tid = threadIdx.x;
    const int lane = tid & 31, wid = tid >> 5;
    const int wm = wid & 3, wn = wid >> 2;
    const int z = blockIdx.z;
    const int row0 = blockIdx.y << 7, col0 = blockIdx.x << 7;
    const int wsel = (mode == 0) ? z : 3;
    const __nv_bfloat16* Bhi = g_whi + (size_t)wsel * HID * HID;
    const __nv_bfloat16* Blo = g_wlo + (size_t)wsel * HID * HID;

    float acc[2][8][4];
#pragma unroll
    for (int t = 0; t < 2; ++t)
#pragma unroll
        for (int j = 0; j < 8; ++j)
#pragma unroll
            for (int e = 0; e < 4; ++e) acc[t][j][e] = 0.f;

    const int lrow = tid >> 1;
    const int lch  = (tid & 1) * 2;
    const uint32_t s_off = lrow * 80 + lch * 16;

    const int a_row = wm * 32 + (lane & 15);
    const int a_ch  = lane >> 4;
    const int b_row = wn * 64 + (lane & 7) + ((lane & 16) >> 1);
    const int b_ch  = (lane >> 3) & 1;

    auto stage_load = [&](int it, int s) {
        const int k0 = it * 32;
        const size_t ga = (size_t)(row0 + lrow) * HID + k0 + lch * 8;
        const size_t gb = (size_t)(col0 + lrow) * HID + k0 + lch * 8;
        const uint32_t d = S0 + s * (4 * TILEB) + s_off;
        cp16(d,                 Ahi + ga); cp16(d + 16,             Ahi + ga + 8);
        cp16(d + TILEB,         Alo + ga); cp16(d + TILEB + 16,     Alo + ga + 8);
        cp16(d + 2 * TILEB,     Bhi + gb); cp16(d + 2 * TILEB + 16, Bhi + gb + 8);
        cp16(d + 3 * TILEB,     Blo + gb); cp16(d + 3 * TILEB + 16, Blo + gb + 8);
    };

    stage_load(0, 0);
    CP_COMMIT();

    for (int it = 0; it < HID / 32; ++it) {
        const int s = it & 1;
        if (it + 1 < HID / 32) {
            stage_load(it + 1, s ^ 1);
            CP_COMMIT();
            CP_WAIT1();
        } else {
            CP_WAIT0();
        }
        __syncthreads();

        const uint32_t uAh = S0 + s * (4 * TILEB);
        const uint32_t uAl = uAh + TILEB;
        const uint32_t uBh = uAh + 2 * TILEB;
        const uint32_t uBl = uAh + 3 * TILEB;
#pragma unroll
        for (int kh = 0; kh < 2; ++kh) {
            uint32_t aH[2][4], aL[2][4], bH[4][4], bL[4][4];
            const uint32_t a_off = a_row * 80 + (kh * 2 + a_ch) * 16;
            const uint32_t b_off = b_row * 80 + (kh * 2 + b_ch) * 16;
            ldsm_x4(aH[0], uAh + a_off);
            ldsm_x4(aH[1], uAh + a_off + 16 * 80);
            ldsm_x4(aL[0], uAl + a_off);
            ldsm_x4(aL[1], uAl + a_off + 16 * 80);
#pragma unroll
            for (int g = 0; g < 4; ++g) {
                ldsm_x4(bH[g], uBh + b_off + g * (16 * 80));
                ldsm_x4(bL[g], uBl + b_off + g * (16 * 80));
            }
#pragma unroll
            for (int t = 0; t < 2; ++t)
#pragma unroll
                for (int g = 0; g < 4; ++g) {
                    mma_bf16(acc[t][2 * g],     aH[t], &bH[g][0]);
                    mma_bf16(acc[t][2 * g + 1], aH[t], &bH[g][2]);
                }
#pragma unroll
            for (int t = 0; t < 2; ++t)
#pragma unroll
                for (int g = 0; g < 4; ++g) {
                    mma_bf16(acc[t][2 * g],     aH[t], &bL[g][0]);
                    mma_bf16(acc[t][2 * g + 1], aH[t], &bL[g][2]);
                }
#pragma unroll
            for (int t = 0; t < 2; ++t)
#pragma unroll
                for (int g = 0; g < 4; ++g) {
                    mma_bf16(acc[t][2 * g],     aL[t], &bH[g][0]);
                    mma_bf16(acc[t][2 * g + 1], aL[t], &bH[g][2]);
                }
        }
        __syncthreads();
    }

    // ---------------- epilogue ----------------
    const int q2 = (lane & 3) * 2;
#pragma unroll
    for (int t = 0; t < 2; ++t) {
#pragma unroll
        for (int h2 = 0; h2 < 2; ++h2) {
            const int row = row0 + wm * 32 + t * 16 + (lane >> 2) + h2 * 8;
            if (mode == 1) {
                float* dst = outp + (size_t)row * HID + col0 + wn * 64 + q2;
#pragma unroll
                for (int j = 0; j < 8; ++j)
                    *(float2*)(dst + j * 8) =
                        make_float2(acc[t][j][h2 * 2], acc[t][j][h2 * 2 + 1]);
            } else {
                const int b_ = row >> 11, s_ = row & (SEQ - 1);
                const int h = (col0 >> 6) + wn;
                const size_t base = ((size_t)(b_ * NHEAD + h) * SEQ + s_) * HDIM;
                if (z == 2) {
#pragma unroll
                    for (int j = 0; j < 8; ++j)
                        *(uint32_t*)(g_vh + base + j * 8 + q2) =
                            packh2(acc[t][j][h2 * 2], acc[t][j][h2 * 2 + 1]);
                } else {
                    const int pos = pos_ids[b_ * SEQ + s_];
                    const float* cr = cosb + pos * HDIM;
                    const float* sr = sinb + pos * HDIM;
                    __half* dh = (z == 0) ? g_qh : g_kh;
                    const float sc_ = (z == 0) ? SCALE : 1.0f;
#pragma unroll
                    for (int j = 0; j < 4; ++j) {
                        float o1[2], o2[2];
#pragma unroll
                        for (int e = 0; e < 2; ++e) {
                            const int d = j * 8 + q2 + e;
                            const float x = acc[t][j][h2 * 2 + e];
                            const float y = acc[t][j + 4][h2 * 2 + e];
                            o1[e] = (x * cr[d] - y * sr[d]) * sc_;
                            o2[e] = (y * cr[d + 32] + x * sr[d + 32]) * sc_;
                        }
                        *(uint32_t*)(dh + base + j * 8 + q2)      = packh2(o1[0], o1[1]);
                        *(uint32_t*)(dh + base + j * 8 + q2 + 32) = packh2(o2[0], o2[1]);
                    }
                }
            }
        }
    }
}

// ---------------------------------------------------------------------------
// fp16 HMMA flash attention: single-product S and PV (3x fewer MMAs).
// 4-buffer cp.async ring, S(kt+1) prefetch overlapped with softmax(kt)/PV(kt).
// ---------------------------------------------------------------------------
#define AP  144    // bytes per smem row (64 fp16 + pad)
#define KT_ 9216   // 64 rows * AP
#define NBUF 4

__global__ __launch_bounds__(256) void attn_kernel()
{
    extern __shared__ char dsm[];
    const uint32_t S0 = smem_u32(dsm);

    const int tid = threadIdx.x, lane = tid & 31, wid = tid >> 5;
    const int qi = gridDim.x - 1 - blockIdx.x;
    const int h = blockIdx.y, b_ = blockIdx.z;
    const int q0 = qi << 7;
    const size_t hb = (size_t)(b_ * NHEAD + h) * SEQ * HDIM;
    const __half *qh = g_qh + hb, *kh = g_kh + hb, *vh = g_vh + hb;

    // ---- stage Q (fp16): rows 0-63 -> buf0 K region, 64-127 -> buf0 V region
    {
        const int r = tid >> 1, half = tid & 1;
        const __half* sh = qh + (size_t)(q0 + r) * HDIM + half * 32;
        const uint32_t dh = S0 + ((r < 64) ? 0 : KT_) + (r & 63) * AP + half * 64;
#pragma unroll
        for (int c = 0; c < 4; ++c)
            cp16(dh + c * 16, sh + c * 8);
    }
    CP_COMMIT();
    CP_WAIT0();
    __syncthreads();

    // ---- Q fragments (fp16) ----
    uint32_t qf[4][4];
    {
        const uint32_t bh = S0 + ((wid < 4) ? 0 : KT_);
        const int arow = (wid & 3) * 16 + (lane & 15);
        const int ach = lane >> 4;
#pragma unroll
        for (int kc = 0; kc < 4; ++kc)
            ldsm_x4(qf[kc], bh + arow * AP + (kc * 2 + ach) * 16);
    }
    __syncthreads();   // Q reads done before KV overwrites buf0

    float oacc[8][4];
#pragma unroll
    for (int g = 0; g < 8; ++g)
#pragma unroll
        for (int e = 0; e < 4; ++e) oacc[g][e] = 0.f;
    float m0 = -1e30f, m1 = -1e30f, l0 = 0.f, l1 = 0.f;

    const int wbase = q0 + wid * 16;
    const int nt = (q0 >> 6) + 2;
    const int lrow = tid >> 2, lq = tid & 3;
    const int brow_ = (lane & 7) + ((lane & 16) >> 1);
    const int bch_ = (lane >> 3) & 1;
    const int vrow_ = lane & 15;
    const int vcol_ = (lane & 16) ? 8 : 0;

    auto kv_load = [&](int kt) {
        const int k0 = kt << 6;
        const size_t src = (size_t)(k0 + lrow) * HDIM + lq * 16;
        const uint32_t d = S0 + (kt & (NBUF - 1)) * (2 * KT_) + lrow * AP + lq * 32;
        cp16(d,           kh + src); cp16(d + 16,       kh + src + 8);
        cp16(d + KT_,     vh + src); cp16(d + KT_ + 16, vh + src + 8);
    };

    auto qk = [&](float (&sc)[8][4], int kt) {
        const uint32_t uK = S0 + (kt & (NBUF - 1)) * (2 * KT_);
#pragma unroll
        for (int g = 0; g < 8; ++g)
#pragma unroll
            for (int e = 0; e < 4; ++e) sc[g][e] = 0.f;
#pragma unroll
        for (int kc = 0; kc < 4; ++kc) {
#pragma unroll
            for (int g = 0; g < 4; ++g) {
                uint32_t bK[4];
                ldsm_x4(bK, uK + (g * 16 + brow_) * AP + (kc * 2 + bch_) * 16);
                mma_f16(sc[2 * g],     qf[kc], &bK[0]);
                mma_f16(sc[2 * g + 1], qf[kc], &bK[2]);
            }
        }
    };

    auto smax_pv = [&](float (&sc)[8][4], int kt) {
        const int k0 = kt << 6;
        const int r0 = wbase + (lane >> 2), r1 = r0 + 8;
        if (k0 + 63 > wbase) {
#pragma unroll
            for (int g = 0; g < 8; ++g) {
#pragma unroll
                for (int e = 0; e < 2; ++e) {
                    const int col = k0 + 8 * g + 2 * (lane & 3) + e;
                    if (col > r0) sc[g][e] = -1e9f;
                    if (col > r1) sc[g][2 + e] = -1e9f;
                }
            }
        }
        float mx0 = sc[0][0], mx1 = sc[0][2];
#pragma unroll
        for (int g = 0; g < 8; ++g) {
            mx0 = fmaxf(mx0, fmaxf(sc[g][0], sc[g][1]));
            mx1 = fmaxf(mx1, fmaxf(sc[g][2], sc[g][3]));
        }
        mx0 = fmaxf(mx0, __shfl_xor_sync(0xffffffffu, mx0, 1));
        mx0 = fmaxf(mx0, __shfl_xor_sync(0xffffffffu, mx0, 2));
        mx1 = fmaxf(mx1, __shfl_xor_sync(0xffffffffu, mx1, 1));
        mx1 = fmaxf(mx1, __shfl_xor_sync(0xffffffffu, mx1, 2));
        const float nm0 = fmaxf(m0, mx0), nm1 = fmaxf(m1, mx1);
        const float cr0 = __expf(m0 - nm0), cr1 = __expf(m1 - nm1);
        m0 = nm0; m1 = nm1;
        float rs0 = 0.f, rs1 = 0.f;
#pragma unroll
        for (int g = 0; g < 8; ++g) {
            sc[g][0] = __expf(sc[g][0] - nm0);
            sc[g][1] = __expf(sc[g][1] - nm0);
            sc[g][2] = __expf(sc[g][2] - nm1);
            sc[g][3] = __expf(sc[g][3] - nm1);
            rs0 += sc[g][0] + sc[g][1];
            rs1 += sc[g][2] + sc[g][3];
        }
        rs0 += __shfl_xor_sync(0xffffffffu, rs0, 1);
        rs0 += __shfl_xor_sync(0xffffffffu, rs0, 2);
        rs1 += __shfl_xor_sync(0xffffffffu, rs1, 1);
        rs1 += __shfl_xor_sync(0xffffffffu, rs1, 2);
        l0 = l0 * cr0 + rs0;
        l1 = l1 * cr1 + rs1;
#pragma unroll
        for (int g = 0; g < 8; ++g) {
            oacc[g][0] *= cr0; oacc[g][1] *= cr0;
            oacc[g][2] *= cr1; oacc[g][3] *= cr1;
        }
        uint32_t pa[4][4];
#pragma unroll
        for (int kc = 0; kc < 4; ++kc) {
            pa[kc][0] = packh2(sc[2 * kc][0],     sc[2 * kc][1]);
            pa[kc][1] = packh2(sc[2 * kc][2],     sc[2 * kc][3]);
            pa[kc][2] = packh2(sc[2 * kc + 1][0], sc[2 * kc + 1][1]);
            pa[kc][3] = packh2(sc[2 * kc + 1][2], sc[2 * kc + 1][3]);
        }
        const uint32_t uV = S0 + (kt & (NBUF - 1)) * (2 * KT_) + KT_;
#pragma unroll
        for (int kc = 0; kc < 4; ++kc) {
#pragma unroll
            for (int dg = 0; dg < 4; ++dg) {
                uint32_t vF[4];
                ldsm_x4_t(vF, uV + (kc * 16 + vrow_) * AP + (dg * 16 + vcol_) * 2);
                mma_f16(oacc[2 * dg],     pa[kc], &vF[0]);
                mma_f16(oacc[2 * dg + 1], pa[kc], &vF[2]);
            }
        }
    };

    auto iter = [&](float (&cur)[8][4], float (&nxt)[8][4], int kt) {
        if (kt + 2 < nt) kv_load(kt + 2);
        CP_COMMIT();
        CP_WAIT1();
        __syncthreads();
        const bool act  = (kt << 6) <= wbase + 15;
        const bool nact = (kt + 1 < nt) && (((kt + 1) << 6) <= wbase + 15);
        if (nact) qk(nxt, kt + 1);
        if (act)  smax_pv(cur, kt);
    };

    // ---- prologue ----
    float scA[8][4], scB[8][4];
    kv_load(0);
    CP_COMMIT();
    if (nt > 1) kv_load(1);
    CP_COMMIT();
    CP_WAIT1();
    __syncthreads();
    qk(scA, 0);

    for (int kt = 0; kt < nt; ) {
        iter(scA, scB, kt); ++kt;
        if (kt < nt) { iter(scB, scA, kt); ++kt; }
    }

    // ---- epilogue: normalize, write ctx as bf16 hi/lo ----
    const float inv0 = 1.f / l0, inv1 = 1.f / l1;
    const int r0 = wbase + (lane >> 2);
    const int colb = h * HDIM + 2 * (lane & 3);
    const size_t ro0 = (size_t)(b_ * SEQ + r0) * HID + colb;
    const size_t ro1 = ro0 + (size_t)8 * HID;
#pragma unroll
    for (int g = 0; g < 8; ++g) {
        uint32_t hi, lo;
        split2(oacc[g][0] * inv0, oacc[g][1] * inv0, hi, lo);
        *(uint32_t*)(g_chi + ro0 + 8 * g) = hi;
        *(uint32_t*)(g_clo + ro0 + 8 * g) = lo;
        split2(oacc[g][2] * inv1, oacc[g][3] * inv1, hi, lo);
        *(uint32_t*)(g_chi + ro1 + 8 * g) = hi;
        *(uint32_t*)(g_clo + ro1 + 8 * g) = lo;
    }
}

// ---------------------------------------------------------------------------
extern "C" void kernel_launch(void* const* d_in, const int* in_sizes, int n_in,
                              void* d_out, int out_size)
{
    const float* X    = (const float*)d_in[0];
    const int*   pos  = (const int*)  d_in[2];
    const float* cosb = (const float*)d_in[3];
    const float* sinb = (const float*)d_in[4];
    const float* Wq   = (const float*)d_in[5];
    const float* Wk   = (const float*)d_in[6];
    const float* Wv   = (const float*)d_in[7];
    const float* Wo   = (const float*)d_in[8];
    float* out = (float*)d_out;

    static int attr_done = 0;
    if (!attr_done) {
        cudaFuncSetAttribute(hgemm_kernel, cudaFuncAttributeMaxDynamicSharedMemorySize,
                             2 * 4 * TILEB);
        cudaFuncSetAttribute(attn_kernel, cudaFuncAttributeMaxDynamicSharedMemorySize,
                             NBUF * 2 * KT_);
        attr_done = 1;
    }

    __nv_bfloat16 *xhi, *xlo, *chi, *clo;
    cudaGetSymbolAddress((void**)&xhi, g_xhi);
    cudaGetSymbolAddress((void**)&xlo, g_xlo);
    cudaGetSymbolAddress((void**)&chi, g_chi);
    cudaGetSymbolAddress((void**)&clo, g_clo);

    // 1) convert inputs to bf16 hi/lo
    {
        int n8 = BATCH * SEQ * HID / 8;
        split_rows_kernel<<<(n8 + 255) / 256, 256>>>(X, xhi, xlo, n8);
        dim3 gw(HID / 32, HID / 32, 4);
        split_wT_kernel<<<gw, dim3(32, 8)>>>(Wq, Wk, Wv, Wo);
    }
    // 2) QKV projection + RoPE (HMMA bf16 3-product) -> fp16 Q,K,V
    {
        dim3 g(HID / 128, (BATCH * SEQ) / 128, 3);
        hgemm_kernel<<<g, 256, 2 * 4 * TILEB>>>(xhi, xlo, 0, pos, cosb, sinb, nullptr);
    }
    // 3) attention (fp16 single-product flash) -> ctx bf16 hi/lo
    {
        dim3 g(SEQ / 128, NHEAD, BATCH);
        attn_kernel<<<g, 256, NBUF * 2 * KT_>>>();
    }
    // 4) output projection (HMMA bf16 3-product)
    {
        dim3 g(HID / 128, (BATCH * SEQ) / 128, 1);
        hgemm_kernel<<<g, 256, 2 * 4 * TILEB>>>(chi, clo, 1, pos, cosb, sinb, out);
    }
}

// round 10
// speedup vs baseline: 1.6134x; 1.3001x over previous
#include <cuda_runtime.h>
#include <cuda_bf16.h>
#include <cuda_fp16.h>
#include <cstdint>

#define BATCH 2
#define SEQ   2048
#define HID   1024
#define NHEAD 16
#define HDIM  64
#define SCALE 0.125f

// ---------------- device scratch (static allocations only) ----------------
__device__ __half g_xh[BATCH * SEQ * HID];     // X hi
__device__ __half g_xl[BATCH * SEQ * HID];     // X lo (fp16 residual)
__device__ __half g_wh[4 * HID * HID];         // W^T fp16 single, mats q,k,v,o
__device__ __half g_ch[BATCH * SEQ * HID];     // ctx hi
__device__ __half g_cl[BATCH * SEQ * HID];     // ctx lo
__device__ __half g_qh[BATCH * NHEAD * SEQ * HDIM];
__device__ __half g_kh[BATCH * NHEAD * SEQ * HDIM];
__device__ __half g_vh[BATCH * NHEAD * SEQ * HDIM];

// ---------------- helpers ----------------
__device__ __forceinline__ uint32_t smem_u32(const void* p) {
    uint32_t a;
    asm("{ .reg .u64 t; cvta.to.shared.u64 t, %1; cvt.u32.u64 %0, t; }" : "=r"(a) : "l"(p));
    return a;
}
__device__ __forceinline__ void ldsm_x4(uint32_t* r, uint32_t addr) {
    asm volatile("ldmatrix.sync.aligned.m8n8.x4.shared.b16 {%0,%1,%2,%3}, [%4];"
                 : "=r"(r[0]), "=r"(r[1]), "=r"(r[2]), "=r"(r[3]) : "r"(addr));
}
__device__ __forceinline__ void ldsm_x4_t(uint32_t* r, uint32_t addr) {
    asm volatile("ldmatrix.sync.aligned.m8n8.x4.trans.shared.b16 {%0,%1,%2,%3}, [%4];"
                 : "=r"(r[0]), "=r"(r[1]), "=r"(r[2]), "=r"(r[3]) : "r"(addr));
}
__device__ __forceinline__ void mma_f16(float* c, const uint32_t* a, const uint32_t* b) {
    asm volatile(
        "mma.sync.aligned.m16n8k16.row.col.f32.f16.f16.f32 "
        "{%0,%1,%2,%3},{%4,%5,%6,%7},{%8,%9},{%0,%1,%2,%3};"
        : "+f"(c[0]), "+f"(c[1]), "+f"(c[2]), "+f"(c[3])
        : "r"(a[0]), "r"(a[1]), "r"(a[2]), "r"(a[3]), "r"(b[0]), "r"(b[1]));
}
__device__ __forceinline__ uint32_t packh2(float a, float b) {
    __half2 h = __floats2half2_rn(a, b);
    return *(uint32_t*)&h;
}
__device__ __forceinline__ void split2h(float a, float b, uint32_t& hi, uint32_t& lo) {
    __half2 h = __floats2half2_rn(a, b);
    float2 hf = __half22float2(h);
    __half2 l = __floats2half2_rn(a - hf.x, b - hf.y);
    hi = *(uint32_t*)&h;
    lo = *(uint32_t*)&l;
}
__device__ __forceinline__ void cp16(uint32_t dst, const void* src) {
    asm volatile("cp.async.cg.shared.global [%0], [%1], 16;" :: "r"(dst), "l"(src));
}
#define CP_COMMIT() asm volatile("cp.async.commit_group;" ::: "memory")
#define CP_WAIT0()  asm volatile("cp.async.wait_group 0;" ::: "memory")
#define CP_WAIT1()  asm volatile("cp.async.wait_group 1;" ::: "memory")

// ---------------- convert kernels ----------------
union HPack { __half b[8]; uint4 v; };

__global__ void split_rows_kernel(const float* __restrict__ in,
                                  __half* __restrict__ hi,
                                  __half* __restrict__ lo, int n8) {
    int i = blockIdx.x * blockDim.x + threadIdx.x;
    if (i >= n8) return;
    float f[8];
    *(float4*)(f)     = ((const float4*)in)[i * 2];
    *(float4*)(f + 4) = ((const float4*)in)[i * 2 + 1];
    HPack h, l;
#pragma unroll
    for (int j = 0; j < 8; ++j) {
        h.b[j] = __float2half_rn(f[j]);
        l.b[j] = __float2half_rn(f[j] - __half2float(h.b[j]));
    }
    ((uint4*)hi)[i] = h.v;
    ((uint4*)lo)[i] = l.v;
}

__global__ void split_wT_kernel(const float* __restrict__ Wq, const float* __restrict__ Wk,
                                const float* __restrict__ Wv, const float* __restrict__ Wo) {
    __shared__ float t[32][33];
    const int mat = blockIdx.z;
    const float* W = (mat == 0) ? Wq : (mat == 1) ? Wk : (mat == 2) ? Wv : Wo;
    __half* dst = g_wh + (size_t)mat * HID * HID;
    const int n0 = blockIdx.x * 32, k0 = blockIdx.y * 32;
    const int tx = threadIdx.x, ty = threadIdx.y;
#pragma unroll
    for (int i = 0; i < 4; ++i)
        t[ty + 8 * i][tx] = W[(size_t)(k0 + ty + 8 * i) * HID + n0 + tx];
    __syncthreads();
#pragma unroll
    for (int i = 0; i < 4; ++i)
        dst[(size_t)(n0 + ty + 8 * i) * HID + k0 + tx] = __float2half_rn(t[tx][ty + 8 * i]);
}

// ---------------------------------------------------------------------------
// fp16 2-product GEMM: C = (A_hi + A_lo) x B^T, B single fp16.
// 128x128 CTA tile, BK=32, 8 warps, 2-stage cp.async pipeline, 3 tiles/stage.
// mode 0: QKV + RoPE -> fp16 Q,K,V (Q pre-scaled). mode 1: out-proj -> fp32.
// ---------------------------------------------------------------------------
#define TILEB 10240   // 128 rows * 80 bytes
#define STAGEB (3 * TILEB)

__global__ __launch_bounds__(256, 2) void hgemm_kernel(
    const __half* __restrict__ Ahi, const __half* __restrict__ Alo,
    int mode, const int* __restrict__ pos_ids,
    const float* __restrict__ cosb, const float* __restrict__ sinb,
    float* __restrict__ outp)
{
    extern __shared__ char dsm[];
    const uint32_t S0 = smem_u32(dsm);

    const int tid = threadIdx.x;
    const int lane = tid & 31, wid = tid >> 5;
    const int wm = wid & 3, wn = wid >> 2;
    const int z = blockIdx.z;
    const int row0 = blockIdx.y << 7, col0 = blockIdx.x << 7;
    const int wsel = (mode == 0) ? z : 3;
    const __half* B = g_wh + (size_t)wsel * HID * HID;

    float acc[2][8][4];
#pragma unroll
    for (int t = 0; t < 2; ++t)
#pragma unroll
        for (int j = 0; j < 8; ++j)
#pragma unroll
            for (int e = 0; e < 4; ++e) acc[t][j][e] = 0.f;

    const int lrow = tid >> 1;
    const int lch  = (tid & 1) * 2;
    const uint32_t s_off = lrow * 80 + lch * 16;

    const int a_row = wm * 32 + (lane & 15);
    const int a_ch  = lane >> 4;
    const int b_row = wn * 64 + (lane & 7) + ((lane & 16) >> 1);
    const int b_ch  = (lane >> 3) & 1;

    auto stage_load = [&](int it, int s) {
        const int k0 = it * 32;
        const size_t ga = (size_t)(row0 + lrow) * HID + k0 + lch * 8;
        const size_t gb = (size_t)(col0 + lrow) * HID + k0 + lch * 8;
        const uint32_t d = S0 + s * STAGEB + s_off;
        cp16(d,             Ahi + ga); cp16(d + 16,             Ahi + ga + 8);
        cp16(d + TILEB,     Alo + ga); cp16(d + TILEB + 16,     Alo + ga + 8);
        cp16(d + 2 * TILEB, B   + gb); cp16(d + 2 * TILEB + 16, B   + gb + 8);
    };

    stage_load(0, 0);
    CP_COMMIT();

    for (int it = 0; it < HID / 32; ++it) {
        const int s = it & 1;
        if (it + 1 < HID / 32) {
            stage_load(it + 1, s ^ 1);
            CP_COMMIT();
            CP_WAIT1();
        } else {
            CP_WAIT0();
        }
        __syncthreads();

        const uint32_t uAh = S0 + s * STAGEB;
        const uint32_t uAl = uAh + TILEB;
        const uint32_t uB  = uAh + 2 * TILEB;
#pragma unroll
        for (int kh = 0; kh < 2; ++kh) {
            uint32_t aH[2][4], aL[2][4], bF[4][4];
            const uint32_t a_off = a_row * 80 + (kh * 2 + a_ch) * 16;
            const uint32_t b_off = b_row * 80 + (kh * 2 + b_ch) * 16;
            ldsm_x4(aH[0], uAh + a_off);
            ldsm_x4(aH[1], uAh + a_off + 16 * 80);
            ldsm_x4(aL[0], uAl + a_off);
            ldsm_x4(aL[1], uAl + a_off + 16 * 80);
#pragma unroll
            for (int g = 0; g < 4; ++g)
                ldsm_x4(bF[g], uB + b_off + g * (16 * 80));
            // pass 1: A_hi x B
#pragma unroll
            for (int t = 0; t < 2; ++t)
#pragma unroll
                for (int g = 0; g < 4; ++g) {
                    mma_f16(acc[t][2 * g],     aH[t], &bF[g][0]);
                    mma_f16(acc[t][2 * g + 1], aH[t], &bF[g][2]);
                }
            // pass 2: A_lo x B
#pragma unroll
            for (int t = 0; t < 2; ++t)
#pragma unroll
                for (int g = 0; g < 4; ++g) {
                    mma_f16(acc[t][2 * g],     aL[t], &bF[g][0]);
                    mma_f16(acc[t][2 * g + 1], aL[t], &bF[g][2]);
                }
        }
        __syncthreads();
    }

    // ---------------- epilogue ----------------
    const int q2 = (lane & 3) * 2;
#pragma unroll
    for (int t = 0; t < 2; ++t) {
#pragma unroll
        for (int h2 = 0; h2 < 2; ++h2) {
            const int row = row0 + wm * 32 + t * 16 + (lane >> 2) + h2 * 8;
            if (mode == 1) {
                float* dst = outp + (size_t)row * HID + col0 + wn * 64 + q2;
#pragma unroll
                for (int j = 0; j < 8; ++j)
                    *(float2*)(dst + j * 8) =
                        make_float2(acc[t][j][h2 * 2], acc[t][j][h2 * 2 + 1]);
            } else {
                const int b_ = row >> 11, s_ = row & (SEQ - 1);
                const int h = (col0 >> 6) + wn;
                const size_t base = ((size_t)(b_ * NHEAD + h) * SEQ + s_) * HDIM;
                if (z == 2) {
#pragma unroll
                    for (int j = 0; j < 8; ++j)
                        *(uint32_t*)(g_vh + base + j * 8 + q2) =
                            packh2(acc[t][j][h2 * 2], acc[t][j][h2 * 2 + 1]);
                } else {
                    const int pos = pos_ids[b_ * SEQ + s_];
                    const float* cr = cosb + pos * HDIM;
                    const float* sr = sinb + pos * HDIM;
                    __half* dh = (z == 0) ? g_qh : g_kh;
                    const float sc_ = (z == 0) ? SCALE : 1.0f;
#pragma unroll
                    for (int j = 0; j < 4; ++j) {
                        float o1[2], o2[2];
#pragma unroll
                        for (int e = 0; e < 2; ++e) {
                            const int d = j * 8 + q2 + e;
                            const float x = acc[t][j][h2 * 2 + e];
                            const float y = acc[t][j + 4][h2 * 2 + e];
                            o1[e] = (x * cr[d] - y * sr[d]) * sc_;
                            o2[e] = (y * cr[d + 32] + x * sr[d + 32]) * sc_;
                        }
                        *(uint32_t*)(dh + base + j * 8 + q2)      = packh2(o1[0], o1[1]);
                        *(uint32_t*)(dh + base + j * 8 + q2 + 32) = packh2(o2[0], o2[1]);
                    }
                }
            }
        }
    }
}

// ---------------------------------------------------------------------------
// fp16 HMMA flash attention (unchanged structure from R8; ctx -> fp16 hi/lo).
// ---------------------------------------------------------------------------
#define AP  144    // bytes per smem row (64 fp16 + pad)
#define KT_ 9216   // 64 rows * AP
#define NBUF 4

__global__ __launch_bounds__(256) void attn_kernel()
{
    extern __shared__ char dsm[];
    const uint32_t S0 = smem_u32(dsm);

    const int tid = threadIdx.x, lane = tid & 31, wid = tid >> 5;
    const int qi = gridDim.x - 1 - blockIdx.x;
    const int h = blockIdx.y, b_ = blockIdx.z;
    const int q0 = qi << 7;
    const size_t hb = (size_t)(b_ * NHEAD + h) * SEQ * HDIM;
    const __half *qh = g_qh + hb, *kh = g_kh + hb, *vh = g_vh + hb;

    // ---- stage Q (fp16) ----
    {
        const int r = tid >> 1, half = tid & 1;
        const __half* sh = qh + (size_t)(q0 + r) * HDIM + half * 32;
        const uint32_t dh = S0 + ((r < 64) ? 0 : KT_) + (r & 63) * AP + half * 64;
#pragma unroll
        for (int c = 0; c < 4; ++c)
            cp16(dh + c * 16, sh + c * 8);
    }
    CP_COMMIT();
    CP_WAIT0();
    __syncthreads();

    // ---- Q fragments ----
    uint32_t qf[4][4];
    {
        const uint32_t bh = S0 + ((wid < 4) ? 0 : KT_);
        const int arow = (wid & 3) * 16 + (lane & 15);
        const int ach = lane >> 4;
#pragma unroll
        for (int kc = 0; kc < 4; ++kc)
            ldsm_x4(qf[kc], bh + arow * AP + (kc * 2 + ach) * 16);
    }
    __syncthreads();

    float oacc[8][4];
#pragma unroll
    for (int g = 0; g < 8; ++g)
#pragma unroll
        for (int e = 0; e < 4; ++e) oacc[g][e] = 0.f;
    float m0 = -1e30f, m1 = -1e30f, l0 = 0.f, l1 = 0.f;

    const int wbase = q0 + wid * 16;
    const int nt = (q0 >> 6) + 2;
    const int lrow = tid >> 2, lq = tid & 3;
    const int brow_ = (lane & 7) + ((lane & 16) >> 1);
    const int bch_ = (lane >> 3) & 1;
    const int vrow_ = lane & 15;
    const int vcol_ = (lane & 16) ? 8 : 0;

    auto kv_load = [&](int kt) {
        const int k0 = kt << 6;
        const size_t src = (size_t)(k0 + lrow) * HDIM + lq * 16;
        const uint32_t d = S0 + (kt & (NBUF - 1)) * (2 * KT_) + lrow * AP + lq * 32;
        cp16(d,           kh + src); cp16(d + 16,       kh + src + 8);
        cp16(d + KT_,     vh + src); cp16(d + KT_ + 16, vh + src + 8);
    };

    auto qk = [&](float (&sc)[8][4], int kt) {
        const uint32_t uK = S0 + (kt & (NBUF - 1)) * (2 * KT_);
#pragma unroll
        for (int g = 0; g < 8; ++g)
#pragma unroll
            for (int e = 0; e < 4; ++e) sc[g][e] = 0.f;
#pragma unroll
        for (int kc = 0; kc < 4; ++kc) {
#pragma unroll
            for (int g = 0; g < 4; ++g) {
                uint32_t bK[4];
                ldsm_x4(bK, uK + (g * 16 + brow_) * AP + (kc * 2 + bch_) * 16);
                mma_f16(sc[2 * g],     qf[kc], &bK[0]);
                mma_f16(sc[2 * g + 1], qf[kc], &bK[2]);
            }
        }
    };

    auto smax_pv = [&](float (&sc)[8][4], int kt) {
        const int k0 = kt << 6;
        const int r0 = wbase + (lane >> 2), r1 = r0 + 8;
        if (k0 + 63 > wbase) {
#pragma unroll
            for (int g = 0; g < 8; ++g) {
#pragma unroll
                for (int e = 0; e < 2; ++e) {
                    const int col = k0 + 8 * g + 2 * (lane & 3) + e;
                    if (col > r0) sc[g][e] = -1e9f;
                    if (col > r1) sc[g][2 + e] = -1e9f;
                }
            }
        }
        float mx0 = sc[0][0], mx1 = sc[0][2];
#pragma unroll
        for (int g = 0; g < 8; ++g) {
            mx0 = fmaxf(mx0, fmaxf(sc[g][0], sc[g][1]));
            mx1 = fmaxf(mx1, fmaxf(sc[g][2], sc[g][3]));
        }
        mx0 = fmaxf(mx0, __shfl_xor_sync(0xffffffffu, mx0, 1));
        mx0 = fmaxf(mx0, __shfl_xor_sync(0xffffffffu, mx0, 2));
        mx1 = fmaxf(mx1, __shfl_xor_sync(0xffffffffu, mx1, 1));
        mx1 = fmaxf(mx1, __shfl_xor_sync(0xffffffffu, mx1, 2));
        const float nm0 = fmaxf(m0, mx0), nm1 = fmaxf(m1, mx1);
        const float cr0 = __expf(m0 - nm0), cr1 = __expf(m1 - nm1);
        m0 = nm0; m1 = nm1;
        float rs0 = 0.f, rs1 = 0.f;
#pragma unroll
        for (int g = 0; g < 8; ++g) {
            sc[g][0] = __expf(sc[g][0] - nm0);
            sc[g][1] = __expf(sc[g][1] - nm0);
            sc[g][2] = __expf(sc[g][2] - nm1);
            sc[g][3] = __expf(sc[g][3] - nm1);
            rs0 += sc[g][0] + sc[g][1];
            rs1 += sc[g][2] + sc[g][3];
        }
        rs0 += __shfl_xor_sync(0xffffffffu, rs0, 1);
        rs0 += __shfl_xor_sync(0xffffffffu, rs0, 2);
        rs1 += __shfl_xor_sync(0xffffffffu, rs1, 1);
        rs1 += __shfl_xor_sync(0xffffffffu, rs1, 2);
        l0 = l0 * cr0 + rs0;
        l1 = l1 * cr1 + rs1;
#pragma unroll
        for (int g = 0; g < 8; ++g) {
            oacc[g][0] *= cr0; oacc[g][1] *= cr0;
            oacc[g][2] *= cr1; oacc[g][3] *= cr1;
        }
        uint32_t pa[4][4];
#pragma unroll
        for (int kc = 0; kc < 4; ++kc) {
            pa[kc][0] = packh2(sc[2 * kc][0],     sc[2 * kc][1]);
            pa[kc][1] = packh2(sc[2 * kc][2],     sc[2 * kc][3]);
            pa[kc][2] = packh2(sc[2 * kc + 1][0], sc[2 * kc + 1][1]);
            pa[kc][3] = packh2(sc[2 * kc + 1][2], sc[2 * kc + 1][3]);
        }
        const uint32_t uV = S0 + (kt & (NBUF - 1)) * (2 * KT_) + KT_;
#pragma unroll
        for (int kc = 0; kc < 4; ++kc) {
#pragma unroll
            for (int dg = 0; dg < 4; ++dg) {
                uint32_t vF[4];
                ldsm_x4_t(vF, uV + (kc * 16 + vrow_) * AP + (dg * 16 + vcol_) * 2);
                mma_f16(oacc[2 * dg],     pa[kc], &vF[0]);
                mma_f16(oacc[2 * dg + 1], pa[kc], &vF[2]);
            }
        }
    };

    auto iter = [&](float (&cur)[8][4], float (&nxt)[8][4], int kt) {
        if (kt + 2 < nt) kv_load(kt + 2);
        CP_COMMIT();
        CP_WAIT1();
        __syncthreads();
        const bool act  = (kt << 6) <= wbase + 15;
        const bool nact = (kt + 1 < nt) && (((kt + 1) << 6) <= wbase + 15);
        if (nact) qk(nxt, kt + 1);
        if (act)  smax_pv(cur, kt);
    };

    // ---- prologue ----
    float scA[8][4], scB[8][4];
    kv_load(0);
    CP_COMMIT();
    if (nt > 1) kv_load(1);
    CP_COMMIT();
    CP_WAIT1();
    __syncthreads();
    qk(scA, 0);

    for (int kt = 0; kt < nt; ) {
        iter(scA, scB, kt); ++kt;
        if (kt < nt) { iter(scB, scA, kt); ++kt; }
    }

    // ---- epilogue: normalize, write ctx as fp16 hi/lo ----
    const float inv0 = 1.f / l0, inv1 = 1.f / l1;
    const int r0 = wbase + (lane >> 2);
    const int colb = h * HDIM + 2 * (lane & 3);
    const size_t ro0 = (size_t)(b_ * SEQ + r0) * HID + colb;
    const size_t ro1 = ro0 + (size_t)8 * HID;
#pragma unroll
    for (int g = 0; g < 8; ++g) {
        uint32_t hi, lo;
        split2h(oacc[g][0] * inv0, oacc[g][1] * inv0, hi, lo);
        *(uint32_t*)(g_ch + ro0 + 8 * g) = hi;
        *(uint32_t*)(g_cl + ro0 + 8 * g) = lo;
        split2h(oacc[g][2] * inv1, oacc[g][3] * inv1, hi, lo);
        *(uint32_t*)(g_ch + ro1 + 8 * g) = hi;
        *(uint32_t*)(g_cl + ro1 + 8 * g) = lo;
    }
}

// ---------------------------------------------------------------------------
extern "C" void kernel_launch(void* const* d_in, const int* in_sizes, int n_in,
                              void* d_out, int out_size)
{
    const float* X    = (const float*)d_in[0];
    const int*   pos  = (const int*)  d_in[2];
    const float* cosb = (const float*)d_in[3];
    const float* sinb = (const float*)d_in[4];
    const float* Wq   = (const float*)d_in[5];
    const float* Wk   = (const float*)d_in[6];
    const float* Wv   = (const float*)d_in[7];
    const float* Wo   = (const float*)d_in[8];
    float* out = (float*)d_out;

    static int attr_done = 0;
    if (!attr_done) {
        cudaFuncSetAttribute(hgemm_kernel, cudaFuncAttributeMaxDynamicSharedMemorySize,
                             2 * STAGEB);
        cudaFuncSetAttribute(attn_kernel, cudaFuncAttributeMaxDynamicSharedMemorySize,
                             NBUF * 2 * KT_);
        attr_done = 1;
    }

    __half *xh, *xl, *ch, *cl;
    cudaGetSymbolAddress((void**)&xh, g_xh);
    cudaGetSymbolAddress((void**)&xl, g_xl);
    cudaGetSymbolAddress((void**)&ch, g_ch);
    cudaGetSymbolAddress((void**)&cl, g_cl);

    // 1) convert inputs: X -> fp16 hi/lo, W^T -> fp16
    {
        int n8 = BATCH * SEQ * HID / 8;
        split_rows_kernel<<<(n8 + 255) / 256, 256>>>(X, xh, xl, n8);
        dim3 gw(HID / 32, HID / 32, 4);
        split_wT_kernel<<<gw, dim3(32, 8)>>>(Wq, Wk, Wv, Wo);
    }
    // 2) QKV projection + RoPE (fp16 2-product) -> fp16 Q,K,V
    {
        dim3 g(HID / 128, (BATCH * SEQ) / 128, 3);
        hgemm_kernel<<<g, 256, 2 * STAGEB>>>(xh, xl, 0, pos, cosb, sinb, nullptr);
    }
    // 3) attention (fp16 single-product flash) -> ctx fp16 hi/lo
    {
        dim3 g(SEQ / 128, NHEAD, BATCH);
        attn_kernel<<<g, 256, NBUF * 2 * KT_>>>();
    }
    // 4) output projection (fp16 2-product)
    {
        dim3 g(HID / 128, (BATCH * SEQ) / 128, 1);
        hgemm_kernel<<<g, 256, 2 * STAGEB>>>(ch, cl, 1, pos, cosb, sinb, out);
    }
}

// round 11
// speedup vs baseline: 2.1624x; 1.3402x over previous
#include <cuda_runtime.h>
#include <cuda_bf16.h>
#include <cuda_fp16.h>
#include <cstdint>

#define BATCH 2
#define SEQ   2048
#define HID   1024
#define NHEAD 16
#define HDIM  64
#define SCALE 0.125f

// ---------------- device scratch (static allocations only) ----------------
__device__ __half g_xh[BATCH * SEQ * HID];     // X fp16
__device__ __half g_wh[4 * HID * HID];         // W^T fp16, mats q,k,v,o
__device__ __half g_ch[BATCH * SEQ * HID];     // ctx fp16
__device__ __half g_qh[BATCH * NHEAD * SEQ * HDIM];
__device__ __half g_kh[BATCH * NHEAD * SEQ * HDIM];
__device__ __half g_vh[BATCH * NHEAD * SEQ * HDIM];

// ---------------- helpers ----------------
__device__ __forceinline__ uint32_t smem_u32(const void* p) {
    uint32_t a;
    asm("{ .reg .u64 t; cvta.to.shared.u64 t, %1; cvt.u32.u64 %0, t; }" : "=r"(a) : "l"(p));
    return a;
}
__device__ __forceinline__ void ldsm_x4(uint32_t* r, uint32_t addr) {
    asm volatile("ldmatrix.sync.aligned.m8n8.x4.shared.b16 {%0,%1,%2,%3}, [%4];"
                 : "=r"(r[0]), "=r"(r[1]), "=r"(r[2]), "=r"(r[3]) : "r"(addr));
}
__device__ __forceinline__ void ldsm_x4_t(uint32_t* r, uint32_t addr) {
    asm volatile("ldmatrix.sync.aligned.m8n8.x4.trans.shared.b16 {%0,%1,%2,%3}, [%4];"
                 : "=r"(r[0]), "=r"(r[1]), "=r"(r[2]), "=r"(r[3]) : "r"(addr));
}
__device__ __forceinline__ void mma_f16(float* c, const uint32_t* a, const uint32_t* b) {
    asm volatile(
        "mma.sync.aligned.m16n8k16.row.col.f32.f16.f16.f32 "
        "{%0,%1,%2,%3},{%4,%5,%6,%7},{%8,%9},{%0,%1,%2,%3};"
        : "+f"(c[0]), "+f"(c[1]), "+f"(c[2]), "+f"(c[3])
        : "r"(a[0]), "r"(a[1]), "r"(a[2]), "r"(a[3]), "r"(b[0]), "r"(b[1]));
}
__device__ __forceinline__ uint32_t packh2(float a, float b) {
    __half2 h = __floats2half2_rn(a, b);
    return *(uint32_t*)&h;
}
__device__ __forceinline__ void cp16(uint32_t dst, const void* src) {
    asm volatile("cp.async.cg.shared.global [%0], [%1], 16;" :: "r"(dst), "l"(src));
}
#define CP_COMMIT() asm volatile("cp.async.commit_group;" ::: "memory")
#define CP_WAIT0()  asm volatile("cp.async.wait_group 0;" ::: "memory")
#define CP_WAIT1()  asm volatile("cp.async.wait_group 1;" ::: "memory")

// ---------------- convert kernels ----------------
union HPack { __half b[8]; uint4 v; };

__global__ void to_half_kernel(const float* __restrict__ in,
                               __half* __restrict__ out, int n8) {
    int i = blockIdx.x * blockDim.x + threadIdx.x;
    if (i >= n8) return;
    float f[8];
    *(float4*)(f)     = ((const float4*)in)[i * 2];
    *(float4*)(f + 4) = ((const float4*)in)[i * 2 + 1];
    HPack h;
#pragma unroll
    for (int j = 0; j < 8; ++j) h.b[j] = __float2half_rn(f[j]);
    ((uint4*)out)[i] = h.v;
}

__global__ void half_wT_kernel(const float* __restrict__ Wq, const float* __restrict__ Wk,
                               const float* __restrict__ Wv, const float* __restrict__ Wo) {
    __shared__ float t[32][33];
    const int mat = blockIdx.z;
    const float* W = (mat == 0) ? Wq : (mat == 1) ? Wk : (mat == 2) ? Wv : Wo;
    __half* dst = g_wh + (size_t)mat * HID * HID;
    const int n0 = blockIdx.x * 32, k0 = blockIdx.y * 32;
    const int tx = threadIdx.x, ty = threadIdx.y;
#pragma unroll
    for (int i = 0; i < 4; ++i)
        t[ty + 8 * i][tx] = W[(size_t)(k0 + ty + 8 * i) * HID + n0 + tx];
    __syncthreads();
#pragma unroll
    for (int i = 0; i < 4; ++i)
        dst[(size_t)(n0 + ty + 8 * i) * HID + k0 + tx] = __float2half_rn(t[tx][ty + 8 * i]);
}

// ---------------------------------------------------------------------------
// fp16 single-product GEMM: C = A x B^T.
// 128x128 CTA tile, BK=32, 8 warps, 2-stage cp.async pipeline, 2 tiles/stage.
// mode 0: QKV + RoPE -> fp16 Q,K,V (Q pre-scaled). mode 1: out-proj -> fp32.
// ---------------------------------------------------------------------------
#define TILEB 10240   // 128 rows * 80 bytes
#define STAGEB (2 * TILEB)

__global__ __launch_bounds__(256, 2) void hgemm_kernel(
    const __half* __restrict__ A,
    int mode, const int* __restrict__ pos_ids,
    const float* __restrict__ cosb, const float* __restrict__ sinb,
    float* __restrict__ outp)
{
    extern __shared__ char dsm[];
    const uint32_t S0 = smem_u32(dsm);

    const int tid = threadIdx.x;
    const int lane = tid & 31, wid = tid >> 5;
    const int wm = wid & 3, wn = wid >> 2;
    const int z = blockIdx.z;
    const int row0 = blockIdx.y << 7, col0 = blockIdx.x << 7;
    const int wsel = (mode == 0) ? z : 3;
    const __half* B = g_wh + (size_t)wsel * HID * HID;

    float acc[2][8][4];
#pragma unroll
    for (int t = 0; t < 2; ++t)
#pragma unroll
        for (int j = 0; j < 8; ++j)
#pragma unroll
            for (int e = 0; e < 4; ++e) acc[t][j][e] = 0.f;

    const int lrow = tid >> 1;
    const int lch  = (tid & 1) * 2;
    const uint32_t s_off = lrow * 80 + lch * 16;

    const int a_row = wm * 32 + (lane & 15);
    const int a_ch  = lane >> 4;
    const int b_row = wn * 64 + (lane & 7) + ((lane & 16) >> 1);
    const int b_ch  = (lane >> 3) & 1;

    auto stage_load = [&](int it, int s) {
        const int k0 = it * 32;
        const size_t ga = (size_t)(row0 + lrow) * HID + k0 + lch * 8;
        const size_t gb = (size_t)(col0 + lrow) * HID + k0 + lch * 8;
        const uint32_t d = S0 + s * STAGEB + s_off;
        cp16(d,         A + ga); cp16(d + 16,         A + ga + 8);
        cp16(d + TILEB, B + gb); cp16(d + TILEB + 16, B + gb + 8);
    };

    stage_load(0, 0);
    CP_COMMIT();

    for (int it = 0; it < HID / 32; ++it) {
        const int s = it & 1;
        if (it + 1 < HID / 32) {
            stage_load(it + 1, s ^ 1);
            CP_COMMIT();
            CP_WAIT1();
        } else {
            CP_WAIT0();
        }
        __syncthreads();

        const uint32_t uA = S0 + s * STAGEB;
        const uint32_t uB = uA + TILEB;
#pragma unroll
        for (int kh = 0; kh < 2; ++kh) {
            uint32_t aF[2][4], bF[4][4];
            const uint32_t a_off = a_row * 80 + (kh * 2 + a_ch) * 16;
            const uint32_t b_off = b_row * 80 + (kh * 2 + b_ch) * 16;
            ldsm_x4(aF[0], uA + a_off);
            ldsm_x4(aF[1], uA + a_off + 16 * 80);
#pragma unroll
            for (int g = 0; g < 4; ++g)
                ldsm_x4(bF[g], uB + b_off + g * (16 * 80));
#pragma unroll
            for (int t = 0; t < 2; ++t)
#pragma unroll
                for (int g = 0; g < 4; ++g) {
                    mma_f16(acc[t][2 * g],     aF[t], &bF[g][0]);
                    mma_f16(acc[t][2 * g + 1], aF[t], &bF[g][2]);
                }
        }
        __syncthreads();
    }

    // ---------------- epilogue ----------------
    const int q2 = (lane & 3) * 2;
#pragma unroll
    for (int t = 0; t < 2; ++t) {
#pragma unroll
        for (int h2 = 0; h2 < 2; ++h2) {
            const int row = row0 + wm * 32 + t * 16 + (lane >> 2) + h2 * 8;
            if (mode == 1) {
                float* dst = outp + (size_t)row * HID + col0 + wn * 64 + q2;
#pragma unroll
                for (int j = 0; j < 8; ++j)
                    *(float2*)(dst + j * 8) =
                        make_float2(acc[t][j][h2 * 2], acc[t][j][h2 * 2 + 1]);
            } else {
                const int b_ = row >> 11, s_ = row & (SEQ - 1);
                const int h = (col0 >> 6) + wn;
                const size_t base = ((size_t)(b_ * NHEAD + h) * SEQ + s_) * HDIM;
                if (z == 2) {
#pragma unroll
                    for (int j = 0; j < 8; ++j)
                        *(uint32_t*)(g_vh + base + j * 8 + q2) =
                            packh2(acc[t][j][h2 * 2], acc[t][j][h2 * 2 + 1]);
                } else {
                    const int pos = pos_ids[b_ * SEQ + s_];
                    const float* cr = cosb + pos * HDIM;
                    const float* sr = sinb + pos * HDIM;
                    __half* dh = (z == 0) ? g_qh : g_kh;
                    const float sc_ = (z == 0) ? SCALE : 1.0f;
#pragma unroll
                    for (int j = 0; j < 4; ++j) {
                        float o1[2], o2[2];
#pragma unroll
                        for (int e = 0; e < 2; ++e) {
                            const int d = j * 8 + q2 + e;
                            const float x = acc[t][j][h2 * 2 + e];
                            const float y = acc[t][j + 4][h2 * 2 + e];
                            o1[e] = (x * cr[d] - y * sr[d]) * sc_;
                            o2[e] = (y * cr[d + 32] + x * sr[d + 32]) * sc_;
                        }
                        *(uint32_t*)(dh + base + j * 8 + q2)      = packh2(o1[0], o1[1]);
                        *(uint32_t*)(dh + base + j * 8 + q2 + 32) = packh2(o2[0], o2[1]);
                    }
                }
            }
        }
    }
}

// ---------------------------------------------------------------------------
// fp16 HMMA flash attention (structure unchanged; ctx -> single fp16).
// ---------------------------------------------------------------------------
#define AP  144    // bytes per smem row (64 fp16 + pad)
#define KT_ 9216   // 64 rows * AP
#define NBUF 4

__global__ __launch_bounds__(256) void attn_kernel()
{
    extern __shared__ char dsm[];
    const uint32_t S0 = smem_u32(dsm);

    const int tid = threadIdx.x, lane = tid & 31, wid = tid >> 5;
    const int qi = gridDim.x - 1 - blockIdx.x;
    const int h = blockIdx.y, b_ = blockIdx.z;
    const int q0 = qi << 7;
    const size_t hb = (size_t)(b_ * NHEAD + h) * SEQ * HDIM;
    const __half *qh = g_qh + hb, *kh = g_kh + hb, *vh = g_vh + hb;

    // ---- stage Q (fp16) ----
    {
        const int r = tid >> 1, half = tid & 1;
        const __half* sh = qh + (size_t)(q0 + r) * HDIM + half * 32;
        const uint32_t dh = S0 + ((r < 64) ? 0 : KT_) + (r & 63) * AP + half * 64;
#pragma unroll
        for (int c = 0; c < 4; ++c)
            cp16(dh + c * 16, sh + c * 8);
    }
    CP_COMMIT();
    CP_WAIT0();
    __syncthreads();

    // ---- Q fragments ----
    uint32_t qf[4][4];
    {
        const uint32_t bh = S0 + ((wid < 4) ? 0 : KT_);
        const int arow = (wid & 3) * 16 + (lane & 15);
        const int ach = lane >> 4;
#pragma unroll
        for (int kc = 0; kc < 4; ++kc)
            ldsm_x4(qf[kc], bh + arow * AP + (kc * 2 + ach) * 16);
    }
    __syncthreads();

    float oacc[8][4];
#pragma unroll
    for (int g = 0; g < 8; ++g)
#pragma unroll
        for (int e = 0; e < 4; ++e) oacc[g][e] = 0.f;
    float m0 = -1e30f, m1 = -1e30f, l0 = 0.f, l1 = 0.f;

    const int wbase = q0 + wid * 16;
    const int nt = (q0 >> 6) + 2;
    const int lrow = tid >> 2, lq = tid & 3;
    const int brow_ = (lane & 7) + ((lane & 16) >> 1);
    const int bch_ = (lane >> 3) & 1;
    const int vrow_ = lane & 15;
    const int vcol_ = (lane & 16) ? 8 : 0;

    auto kv_load = [&](int kt) {
        const int k0 = kt << 6;
        const size_t src = (size_t)(k0 + lrow) * HDIM + lq * 16;
        const uint32_t d = S0 + (kt & (NBUF - 1)) * (2 * KT_) + lrow * AP + lq * 32;
        cp16(d,           kh + src); cp16(d + 16,       kh + src + 8);
        cp16(d + KT_,     vh + src); cp16(d + KT_ + 16, vh + src + 8);
    };

    auto qk = [&](float (&sc)[8][4], int kt) {
        const uint32_t uK = S0 + (kt & (NBUF - 1)) * (2 * KT_);
#pragma unroll
        for (int g = 0; g < 8; ++g)
#pragma unroll
            for (int e = 0; e < 4; ++e) sc[g][e] = 0.f;
#pragma unroll
        for (int kc = 0; kc < 4; ++kc) {
#pragma unroll
            for (int g = 0; g < 4; ++g) {
                uint32_t bK[4];
                ldsm_x4(bK, uK + (g * 16 + brow_) * AP + (kc * 2 + bch_) * 16);
                mma_f16(sc[2 * g],     qf[kc], &bK[0]);
                mma_f16(sc[2 * g + 1], qf[kc], &bK[2]);
            }
        }
    };

    auto smax_pv = [&](float (&sc)[8][4], int kt) {
        const int k0 = kt << 6;
        const int r0 = wbase + (lane >> 2), r1 = r0 + 8;
        if (k0 + 63 > wbase) {
#pragma unroll
            for (int g = 0; g < 8; ++g) {
#pragma unroll
                for (int e = 0; e < 2; ++e) {
                    const int col = k0 + 8 * g + 2 * (lane & 3) + e;
                    if (col > r0) sc[g][e] = -1e9f;
                    if (col > r1) sc[g][2 + e] = -1e9f;
                }
            }
        }
        float mx0 = sc[0][0], mx1 = sc[0][2];
#pragma unroll
        for (int g = 0; g < 8; ++g) {
            mx0 = fmaxf(mx0, fmaxf(sc[g][0], sc[g][1]));
            mx1 = fmaxf(mx1, fmaxf(sc[g][2], sc[g][3]));
        }
        mx0 = fmaxf(mx0, __shfl_xor_sync(0xffffffffu, mx0, 1));
        mx0 = fmaxf(mx0, __shfl_xor_sync(0xffffffffu, mx0, 2));
        mx1 = fmaxf(mx1, __shfl_xor_sync(0xffffffffu, mx1, 1));
        mx1 = fmaxf(mx1, __shfl_xor_sync(0xffffffffu, mx1, 2));
        const float nm0 = fmaxf(m0, mx0), nm1 = fmaxf(m1, mx1);
        const float cr0 = __expf(m0 - nm0), cr1 = __expf(m1 - nm1);
        m0 = nm0; m1 = nm1;
        float rs0 = 0.f, rs1 = 0.f;
#pragma unroll
        for (int g = 0; g < 8; ++g) {
            sc[g][0] = __expf(sc[g][0] - nm0);
            sc[g][1] = __expf(sc[g][1] - nm0);
            sc[g][2] = __expf(sc[g][2] - nm1);
            sc[g][3] = __expf(sc[g][3] - nm1);
            rs0 += sc[g][0] + sc[g][1];
            rs1 += sc[g][2] + sc[g][3];
        }
        rs0 += __shfl_xor_sync(0xffffffffu, rs0, 1);
        rs0 += __shfl_xor_sync(0xffffffffu, rs0, 2);
        rs1 += __shfl_xor_sync(0xffffffffu, rs1, 1);
        rs1 += __shfl_xor_sync(0xffffffffu, rs1, 2);
        l0 = l0 * cr0 + rs0;
        l1 = l1 * cr1 + rs1;
#pragma unroll
        for (int g = 0; g < 8; ++g) {
            oacc[g][0] *= cr0; oacc[g][1] *= cr0;
            oacc[g][2] *= cr1; oacc[g][3] *= cr1;
        }
        uint32_t pa[4][4];
#pragma unroll
        for (int kc = 0; kc < 4; ++kc) {
            pa[kc][0] = packh2(sc[2 * kc][0],     sc[2 * kc][1]);
            pa[kc][1] = packh2(sc[2 * kc][2],     sc[2 * kc][3]);
            pa[kc][2] = packh2(sc[2 * kc + 1][0], sc[2 * kc + 1][1]);
            pa[kc][3] = packh2(sc[2 * kc + 1][2], sc[2 * kc + 1][3]);
        }
        const uint32_t uV = S0 + (kt & (NBUF - 1)) * (2 * KT_) + KT_;
#pragma unroll
        for (int kc = 0; kc < 4; ++kc) {
#pragma unroll
            for (int dg = 0; dg < 4; ++dg) {
                uint32_t vF[4];
                ldsm_x4_t(vF, uV + (kc * 16 + vrow_) * AP + (dg * 16 + vcol_) * 2);
                mma_f16(oacc[2 * dg],     pa[kc], &vF[0]);
                mma_f16(oacc[2 * dg + 1], pa[kc], &vF[2]);
            }
        }
    };

    auto iter = [&](float (&cur)[8][4], float (&nxt)[8][4], int kt) {
        if (kt + 2 < nt) kv_load(kt + 2);
        CP_COMMIT();
        CP_WAIT1();
        __syncthreads();
        const bool act  = (kt << 6) <= wbase + 15;
        const bool nact = (kt + 1 < nt) && (((kt + 1) << 6) <= wbase + 15);
        if (nact) qk(nxt, kt + 1);
        if (act)  smax_pv(cur, kt);
    };

    // ---- prologue ----
    float scA[8][4], scB[8][4];
    kv_load(0);
    CP_COMMIT();
    if (nt > 1) kv_load(1);
    CP_COMMIT();
    CP_WAIT1();
    __syncthreads();
    qk(scA, 0);

    for (int kt = 0; kt < nt; ) {
        iter(scA, scB, kt); ++kt;
        if (kt < nt) { iter(scB, scA, kt); ++kt; }
    }

    // ---- epilogue: normalize, write ctx as fp16 ----
    const float inv0 = 1.f / l0, inv1 = 1.f / l1;
    const int r0 = wbase + (lane >> 2);
    const int colb = h * HDIM + 2 * (lane & 3);
    const size_t ro0 = (size_t)(b_ * SEQ + r0) * HID + colb;
    const size_t ro1 = ro0 + (size_t)8 * HID;
#pragma unroll
    for (int g = 0; g < 8; ++g) {
        *(uint32_t*)(g_ch + ro0 + 8 * g) = packh2(oacc[g][0] * inv0, oacc[g][1] * inv0);
        *(uint32_t*)(g_ch + ro1 + 8 * g) = packh2(oacc[g][2] * inv1, oacc[g][3] * inv1);
    }
}

// ---------------------------------------------------------------------------
extern "C" void kernel_launch(void* const* d_in, const int* in_sizes, int n_in,
                              void* d_out, int out_size)
{
    const float* X    = (const float*)d_in[0];
    const int*   pos  = (const int*)  d_in[2];
    const float* cosb = (const float*)d_in[3];
    const float* sinb = (const float*)d_in[4];
    const float* Wq   = (const float*)d_in[5];
    const float* Wk   = (const float*)d_in[6];
    const float* Wv   = (const float*)d_in[7];
    const float* Wo   = (const float*)d_in[8];
    float* out = (float*)d_out;

    static int attr_done = 0;
    if (!attr_done) {
        cudaFuncSetAttribute(hgemm_kernel, cudaFuncAttributeMaxDynamicSharedMemorySize,
                             2 * STAGEB);
        cudaFuncSetAttribute(attn_kernel, cudaFuncAttributeMaxDynamicSharedMemorySize,
                             NBUF * 2 * KT_);
        attr_done = 1;
    }

    __half *xh, *ch;
    cudaGetSymbolAddress((void**)&xh, g_xh);
    cudaGetSymbolAddress((void**)&ch, g_ch);

    // 1) convert inputs: X -> fp16, W^T -> fp16
    {
        int n8 = BATCH * SEQ * HID / 8;
        to_half_kernel<<<(n8 + 255) / 256, 256>>>(X, xh, n8);
        dim3 gw(HID / 32, HID / 32, 4);
        half_wT_kernel<<<gw, dim3(32, 8)>>>(Wq, Wk, Wv, Wo);
    }
    // 2) QKV projection + RoPE (fp16 single-product) -> fp16 Q,K,V
    {
        dim3 g(HID / 128, (BATCH * SEQ) / 128, 3);
        hgemm_kernel<<<g, 256, 2 * STAGEB>>>(xh, 0, pos, cosb, sinb, nullptr);
    }
    // 3) attention (fp16 single-product flash) -> ctx fp16
    {
        dim3 g(SEQ / 128, NHEAD, BATCH);
        attn_kernel<<<g, 256, NBUF * 2 * KT_>>>();
    }
    // 4) output projection (fp16 single-product)
    {
        dim3 g(HID / 128, (BATCH * SEQ) / 128, 1);
        hgemm_kernel<<<g, 256, 2 * STAGEB>>>(ch, 1, pos, cosb, sinb, out);
    }
}